// round 1
// baseline (speedup 1.0000x reference)
#include <cuda_runtime.h>
#include <math.h>

#define BSZ 16
#define CC  256
#define SSZ 1024
#define NHD 8
#define NG  16
#define CPG 16
#define EPSV 1e-5f

// Scratch (static device arrays; allocation-free per harness rules)
__device__ __align__(128) float g_norm[2 * BSZ * CC * SSZ];        // 33.5 MB
__device__ __align__(128) float g_qkv [2 * BSZ * 3 * CC * SSZ];    // 100.7 MB
__device__ __align__(128) float g_attn[2 * BSZ * CC * SSZ];        // 33.5 MB

// ---------------------------------------------------------------------------
// GroupNorm: one block per (batch, group); 16 channels x 1024 = 16384 elems
// ---------------------------------------------------------------------------
__global__ void groupnorm_kernel(const float* __restrict__ x,
                                 const float* __restrict__ gamma,
                                 const float* __restrict__ beta,
                                 float* __restrict__ out) {
    int bg = blockIdx.x;
    int b = bg / NG, g = bg % NG;
    const int n = CPG * SSZ;                  // 16384
    const float* xp = x + (size_t)(b * CC + g * CPG) * SSZ;
    float* op = out + (size_t)(b * CC + g * CPG) * SSZ;
    int tid = threadIdx.x;

    const float4* x4 = (const float4*)xp;
    float s = 0.f, s2 = 0.f;
    #pragma unroll 4
    for (int i = tid; i < n / 4; i += 256) {
        float4 v = x4[i];
        s  += v.x + v.y + v.z + v.w;
        s2 += v.x * v.x + v.y * v.y + v.z * v.z + v.w * v.w;
    }
    __shared__ float rs[256], rs2[256];
    rs[tid] = s; rs2[tid] = s2;
    __syncthreads();
    for (int o = 128; o > 0; o >>= 1) {
        if (tid < o) { rs[tid] += rs[tid + o]; rs2[tid] += rs2[tid + o]; }
        __syncthreads();
    }
    float mu = rs[0] / (float)n;
    float var = rs2[0] / (float)n - mu * mu;
    float rstd = rsqrtf(var + EPSV);

    float4* o4 = (float4*)op;
    for (int i = tid; i < n / 4; i += 256) {
        int c = g * CPG + (i >> 8);           // (i*4)/1024
        float sc = gamma[c] * rstd;
        float sh = beta[c] - mu * sc;
        float4 v = x4[i];
        float4 r;
        r.x = v.x * sc + sh; r.y = v.y * sc + sh;
        r.z = v.z * sc + sh; r.w = v.w * sc + sh;
        o4[i] = r;
    }
}

// ---------------------------------------------------------------------------
// SGEMM: C[M x 1024] = A[M x 256] * B[256 x 1024]  (+ bias + residual)
// 128x128 tile, 256 threads, 8x8 per thread, BK=16. Batched via blockIdx.z.
// ---------------------------------------------------------------------------
template <bool EPI>
__global__ void sgemm128(const float* __restrict__ A,
                         const float* __restrict__ Bm,
                         float* __restrict__ Cm,
                         const float* __restrict__ bias,
                         const float* __restrict__ res,
                         long strideB, long strideC, long strideR) {
    const int K = 256, N = 1024;
    int bz = blockIdx.z;
    const float* Bp = Bm + (size_t)bz * strideB;
    float* Cp = Cm + (size_t)bz * strideC;
    const float* Rp = EPI ? (res + (size_t)bz * strideR) : nullptr;
    int m0 = blockIdx.y * 128, n0 = blockIdx.x * 128;

    __shared__ float As[16][132];
    __shared__ float Bs[16][128];
    int tid = threadIdx.x;
    int tx = tid & 15, ty = tid >> 4;
    float acc[8][8];
    #pragma unroll
    for (int i = 0; i < 8; i++)
        #pragma unroll
        for (int j = 0; j < 8; j++) acc[i][j] = 0.f;

    for (int k0 = 0; k0 < K; k0 += 16) {
        #pragma unroll
        for (int r = 0; r < 2; r++) {
            int idx = tid + r * 256;          // 0..511
            int row = idx >> 2;               // 0..127
            int kq = (idx & 3) << 2;          // 0,4,8,12
            float4 a = *(const float4*)(A + (size_t)(m0 + row) * K + k0 + kq);
            As[kq + 0][row] = a.x; As[kq + 1][row] = a.y;
            As[kq + 2][row] = a.z; As[kq + 3][row] = a.w;
        }
        #pragma unroll
        for (int r = 0; r < 2; r++) {
            int idx = tid + r * 256;
            int row = idx >> 5;               // 0..15
            int c4 = (idx & 31) << 2;
            *(float4*)&Bs[row][c4] =
                *(const float4*)(Bp + (size_t)(k0 + row) * N + n0 + c4);
        }
        __syncthreads();
        #pragma unroll
        for (int k = 0; k < 16; k++) {
            float ra[8], rb[8];
            *(float4*)(ra)     = *(float4*)&As[k][ty * 8];
            *(float4*)(ra + 4) = *(float4*)&As[k][ty * 8 + 4];
            *(float4*)(rb)     = *(float4*)&Bs[k][tx * 8];
            *(float4*)(rb + 4) = *(float4*)&Bs[k][tx * 8 + 4];
            #pragma unroll
            for (int i = 0; i < 8; i++)
                #pragma unroll
                for (int j = 0; j < 8; j++)
                    acc[i][j] += ra[i] * rb[j];
        }
        __syncthreads();
    }

    #pragma unroll
    for (int i = 0; i < 8; i++) {
        int m = m0 + ty * 8 + i;
        float bv = EPI ? bias[m] : 0.f;
        #pragma unroll
        for (int j = 0; j < 8; j += 4) {
            int nn = n0 + tx * 8 + j;
            float4 r;
            r.x = acc[i][j] + bv; r.y = acc[i][j + 1] + bv;
            r.z = acc[i][j + 2] + bv; r.w = acc[i][j + 3] + bv;
            if (EPI) {
                float4 rr = *(const float4*)(Rp + (size_t)m * N + nn);
                r.x += rr.x; r.y += rr.y; r.z += rr.z; r.w += rr.w;
            }
            *(float4*)(Cp + (size_t)m * N + nn) = r;
        }
    }
}

// ---------------------------------------------------------------------------
// Flash attention: CTA = (q_tile 128, b*head). d=32, S=1024, 8 key tiles.
// Scores 128x128 per thread-tile (8x8), P staged in SMEM, 2nd GEMM P*V^T.
// ---------------------------------------------------------------------------
#define SMEM_FLOATS (3 * 32 * 132 + 128 * 132)
#define SMEM_BYTES  (SMEM_FLOATS * 4)

__global__ void attn_kernel(const float* __restrict__ qkv_q,
                            const float* __restrict__ qkv_kv,
                            float* __restrict__ outb) {
    int qt = blockIdx.x;
    int bh = blockIdx.y;
    int b = bh / NHD, h = bh % NHD;
    size_t base = (size_t)b * 3 * CC * SSZ + (size_t)h * 96 * SSZ;
    const float* Qg = qkv_q  + base;            // rows 0..31 of head block
    const float* Kg = qkv_kv + base + 32 * SSZ; // rows 32..63
    const float* Vg = qkv_kv + base + 64 * SSZ; // rows 64..95

    extern __shared__ float sm[];
    float* Qs = sm;                 // [32][132]
    float* Ks = Qs + 32 * 132;      // [32][132]
    float* Vs = Ks + 32 * 132;      // [32][132]
    float* Ps = Vs + 32 * 132;      // [128][132]

    int tid = threadIdx.x;
    int tx = tid & 15, ty = tid >> 4;
    int q0 = qt * 128;
    const float scale = 0.0625f;    // 1/sqrt(256)

    // Load Q tile (32 x 128)
    #pragma unroll
    for (int r = 0; r < 4; r++) {
        int idx = tid + r * 256;    // 1024 float4 units
        int row = idx >> 5;         // 0..31
        int c4 = (idx & 31) << 2;
        *(float4*)&Qs[row * 132 + c4] =
            *(const float4*)(Qg + (size_t)row * SSZ + q0 + c4);
    }

    float m_i[8], l_i[8], oa0[8], oa1[8];
    #pragma unroll
    for (int i = 0; i < 8; i++) { m_i[i] = -1e30f; l_i[i] = 0.f; oa0[i] = 0.f; oa1[i] = 0.f; }

    for (int kt = 0; kt < 8; kt++) {
        int k0c = kt * 128;
        __syncthreads();            // protect Ks/Vs/Ps reuse (and Qs on iter 0)
        #pragma unroll
        for (int r = 0; r < 4; r++) {
            int idx = tid + r * 256;
            int row = idx >> 5;
            int c4 = (idx & 31) << 2;
            *(float4*)&Ks[row * 132 + c4] =
                *(const float4*)(Kg + (size_t)row * SSZ + k0c + c4);
            *(float4*)&Vs[row * 132 + c4] =
                *(const float4*)(Vg + (size_t)row * SSZ + k0c + c4);
        }
        __syncthreads();

        // scores: s[i][j] = sum_d Qs[d][ty*8+i] * Ks[d][tx*8+j]
        float s[8][8];
        #pragma unroll
        for (int i = 0; i < 8; i++)
            #pragma unroll
            for (int j = 0; j < 8; j++) s[i][j] = 0.f;
        #pragma unroll
        for (int d = 0; d < 32; d++) {
            float ra[8], rb[8];
            *(float4*)(ra)     = *(float4*)&Qs[d * 132 + ty * 8];
            *(float4*)(ra + 4) = *(float4*)&Qs[d * 132 + ty * 8 + 4];
            *(float4*)(rb)     = *(float4*)&Ks[d * 132 + tx * 8];
            *(float4*)(rb + 4) = *(float4*)&Ks[d * 132 + tx * 8 + 4];
            #pragma unroll
            for (int i = 0; i < 8; i++)
                #pragma unroll
                for (int j = 0; j < 8; j++)
                    s[i][j] += ra[i] * rb[j];
        }

        // online softmax over this key tile
        #pragma unroll
        for (int i = 0; i < 8; i++) {
            float mx = s[i][0];
            #pragma unroll
            for (int j = 1; j < 8; j++) mx = fmaxf(mx, s[i][j]);
            mx *= scale;
            #pragma unroll
            for (int o = 1; o < 16; o <<= 1)
                mx = fmaxf(mx, __shfl_xor_sync(0xffffffffu, mx, o));
            float m_new = fmaxf(m_i[i], mx);
            float alpha = __expf(m_i[i] - m_new);
            float ls = 0.f;
            #pragma unroll
            for (int j = 0; j < 8; j++) {
                float p = __expf(s[i][j] * scale - m_new);
                s[i][j] = p;
                ls += p;
            }
            #pragma unroll
            for (int o = 1; o < 16; o <<= 1)
                ls += __shfl_xor_sync(0xffffffffu, ls, o);
            l_i[i] = l_i[i] * alpha + ls;
            m_i[i] = m_new;
            oa0[i] *= alpha; oa1[i] *= alpha;
            *(float4*)&Ps[(ty * 8 + i) * 132 + tx * 8]     = *(float4*)&s[i][0];
            *(float4*)&Ps[(ty * 8 + i) * 132 + tx * 8 + 4] = *(float4*)&s[i][4];
        }
        __syncthreads();

        // GEMM2: o[i][cc] += sum_j P[q][j] * V[c][j], c = tx*2 + cc
        int c0 = tx * 2;
        #pragma unroll 4
        for (int j4 = 0; j4 < 128; j4 += 4) {
            float4 v0 = *(float4*)&Vs[c0 * 132 + j4];
            float4 v1 = *(float4*)&Vs[(c0 + 1) * 132 + j4];
            #pragma unroll
            for (int i = 0; i < 8; i++) {
                float4 p = *(float4*)&Ps[(ty * 8 + i) * 132 + j4];
                oa0[i] += p.x * v0.x + p.y * v0.y + p.z * v0.z + p.w * v0.w;
                oa1[i] += p.x * v1.x + p.y * v1.y + p.z * v1.z + p.w * v1.w;
            }
        }
    }

    // Stage (c, q) tile in SMEM (reuse Ps), then coalesced store.
    __syncthreads();
    #pragma unroll
    for (int i = 0; i < 8; i++) {
        float inv = 1.f / l_i[i];
        Ps[(tx * 2 + 0) * 132 + ty * 8 + i] = oa0[i] * inv;
        Ps[(tx * 2 + 1) * 132 + ty * 8 + i] = oa1[i] * inv;
    }
    __syncthreads();
    #pragma unroll
    for (int r = 0; r < 4; r++) {
        int idx = tid + r * 256;    // 1024 float4 units (32 x 128)
        int row = idx >> 5;         // channel within head
        int c4 = (idx & 31) << 2;
        *(float4*)(outb + ((size_t)b * CC + h * 32 + row) * SSZ + q0 + c4) =
            *(float4*)&Ps[row * 132 + c4];
    }
}

// ---------------------------------------------------------------------------
extern "C" void kernel_launch(void* const* d_in, const int* in_sizes, int n_in,
                              void* d_out, int out_size) {
    const float* xA    = (const float*)d_in[0];
    const float* xB    = (const float*)d_in[1];
    const float* gA    = (const float*)d_in[2];
    const float* bA    = (const float*)d_in[3];
    const float* gB    = (const float*)d_in[4];
    const float* bB    = (const float*)d_in[5];
    const float* WqkvA = (const float*)d_in[6];
    const float* WqkvB = (const float*)d_in[7];
    const float* WoutA = (const float*)d_in[8];
    const float* boutA = (const float*)d_in[9];
    const float* WoutB = (const float*)d_in[10];
    const float* boutB = (const float*)d_in[11];
    float* out = (float*)d_out;

    void *pn, *pq, *pa;
    cudaGetSymbolAddress(&pn, g_norm);
    cudaGetSymbolAddress(&pq, g_qkv);
    cudaGetSymbolAddress(&pa, g_attn);
    float* normA = (float*)pn;
    float* normB = normA + (size_t)BSZ * CC * SSZ;
    float* qkvA  = (float*)pq;
    float* qkvB  = qkvA + (size_t)BSZ * 3 * CC * SSZ;
    float* attnA = (float*)pa;
    float* attnB = attnA + (size_t)BSZ * CC * SSZ;

    const long CS = (long)CC * SSZ;          // 262144
    const long Q3 = (long)3 * CC * SSZ;      // 786432

    // 1) GroupNorm
    groupnorm_kernel<<<BSZ * NG, 256>>>(xA, gA, bA, normA);
    groupnorm_kernel<<<BSZ * NG, 256>>>(xB, gB, bB, normB);

    // 2) QKV projections: (768 x 256) x (256 x 1024) per batch
    dim3 gq(8, 6, BSZ);
    sgemm128<false><<<gq, 256>>>(WqkvA, normA, qkvA, nullptr, nullptr, CS, Q3, 0);
    sgemm128<false><<<gq, 256>>>(WqkvB, normB, qkvB, nullptr, nullptr, CS, Q3, 0);

    // 3) Cross attention: out_A uses (qB, kA, vA); out_B uses (qA, kB, vB)
    cudaFuncSetAttribute(attn_kernel,
                         cudaFuncAttributeMaxDynamicSharedMemorySize, SMEM_BYTES);
    dim3 ga(8, BSZ * NHD);
    attn_kernel<<<ga, 256, SMEM_BYTES>>>(qkvB, qkvA, attnA);
    attn_kernel<<<ga, 256, SMEM_BYTES>>>(qkvA, qkvB, attnB);

    // 4) Output projection + bias + residual(norm)
    dim3 gp(8, 2, BSZ);
    sgemm128<true><<<gp, 256>>>(WoutA, attnA, out, boutA, normA, CS, CS, CS);
    sgemm128<true><<<gp, 256>>>(WoutB, attnB, out + (size_t)BSZ * CC * SSZ,
                                boutB, normB, CS, CS, CS);
}

// round 2
// speedup vs baseline: 2.2634x; 2.2634x over previous
#include <cuda_runtime.h>
#include <math.h>
#include <stdint.h>

#define BSZ 16
#define CC  256
#define SSZ 1024
#define NHD 8
#define NG  16
#define CPG 16
#define EPSV 1e-5f

// Scratch (static device arrays; allocation-free per harness rules)
__device__ __align__(128) float g_norm[2 * BSZ * CC * SSZ];
__device__ __align__(128) float g_qkv [2 * BSZ * 3 * CC * SSZ];
__device__ __align__(128) float g_attn[2 * BSZ * CC * SSZ];

__device__ __forceinline__ uint32_t f2tf(float f) {
    uint32_t u;
    asm("cvt.rna.tf32.f32 %0, %1;" : "=r"(u) : "f"(f));
    return u;
}
__device__ __forceinline__ void mma_tf32(float d[4], const uint32_t a[4],
                                         const uint32_t b[2]) {
    asm volatile(
        "mma.sync.aligned.m16n8k8.row.col.f32.tf32.tf32.f32 "
        "{%0,%1,%2,%3}, {%4,%5,%6,%7}, {%8,%9}, {%0,%1,%2,%3};\n"
        : "+f"(d[0]), "+f"(d[1]), "+f"(d[2]), "+f"(d[3])
        : "r"(a[0]), "r"(a[1]), "r"(a[2]), "r"(a[3]), "r"(b[0]), "r"(b[1]));
}

// ---------------------------------------------------------------------------
// GroupNorm (unchanged — memory bound, ~16 us total)
// ---------------------------------------------------------------------------
__global__ void groupnorm_kernel(const float* __restrict__ x,
                                 const float* __restrict__ gamma,
                                 const float* __restrict__ beta,
                                 float* __restrict__ out) {
    int bg = blockIdx.x;
    int b = bg / NG, g = bg % NG;
    const int n = CPG * SSZ;
    const float* xp = x + (size_t)(b * CC + g * CPG) * SSZ;
    float* op = out + (size_t)(b * CC + g * CPG) * SSZ;
    int tid = threadIdx.x;

    const float4* x4 = (const float4*)xp;
    float s = 0.f, s2 = 0.f;
    #pragma unroll 4
    for (int i = tid; i < n / 4; i += 256) {
        float4 v = x4[i];
        s  += v.x + v.y + v.z + v.w;
        s2 += v.x * v.x + v.y * v.y + v.z * v.z + v.w * v.w;
    }
    __shared__ float rs[256], rs2[256];
    rs[tid] = s; rs2[tid] = s2;
    __syncthreads();
    for (int o = 128; o > 0; o >>= 1) {
        if (tid < o) { rs[tid] += rs[tid + o]; rs2[tid] += rs2[tid + o]; }
        __syncthreads();
    }
    float mu = rs[0] / (float)n;
    float var = rs2[0] / (float)n - mu * mu;
    float rstd = rsqrtf(var + EPSV);

    float4* o4 = (float4*)op;
    for (int i = tid; i < n / 4; i += 256) {
        int c = g * CPG + (i >> 8);
        float sc = gamma[c] * rstd;
        float sh = beta[c] - mu * sc;
        float4 v = x4[i];
        float4 r;
        r.x = v.x * sc + sh; r.y = v.y * sc + sh;
        r.z = v.z * sc + sh; r.w = v.w * sc + sh;
        o4[i] = r;
    }
}

// ---------------------------------------------------------------------------
// tf32 MMA GEMM: C[M x 1024] = A[M x 256] * B[256 x 1024] (+bias+residual)
// CTA 128x128, BK=32, 8 warps (64x32 warp tile), m16n8k8 tf32.
// SMEM strides 36/136 make fragment-gather LDS conflict-free.
// ---------------------------------------------------------------------------
template <bool EPI>
__global__ __launch_bounds__(256) void gemm_tf32(
    const float* __restrict__ A, const float* __restrict__ Bm,
    float* __restrict__ Cm, const float* __restrict__ bias,
    const float* __restrict__ res, long strideB, long strideC, long strideR) {
    const int K = 256, N = 1024;
    int bz = blockIdx.z;
    const float* Bp = Bm + (size_t)bz * strideB;
    float* Cp = Cm + (size_t)bz * strideC;
    const float* Rp = EPI ? (res + (size_t)bz * strideR) : nullptr;
    int m0 = blockIdx.y * 128, n0 = blockIdx.x * 128;

    __shared__ __align__(16) float As[128][36];
    __shared__ __align__(16) float Bs[32][136];

    int tid = threadIdx.x;
    int lane = tid & 31, wid = tid >> 5;
    int wy = wid >> 2, wx = wid & 3;
    int lq = lane >> 2, lr = lane & 3;

    float acc[4][4][4];
    #pragma unroll
    for (int i = 0; i < 4; i++)
        #pragma unroll
        for (int j = 0; j < 4; j++)
            #pragma unroll
            for (int c = 0; c < 4; c++) acc[i][j][c] = 0.f;

    for (int k0 = 0; k0 < K; k0 += 32) {
        #pragma unroll
        for (int r = 0; r < 4; r++) {
            int idx = tid + r * 256;          // 1024 float4 over 128x32
            int row = idx >> 3, c4 = (idx & 7) << 2;
            float4 v = *(const float4*)(A + (size_t)(m0 + row) * K + k0 + c4);
            uint4 u = make_uint4(f2tf(v.x), f2tf(v.y), f2tf(v.z), f2tf(v.w));
            *(uint4*)&As[row][c4] = u;
        }
        #pragma unroll
        for (int r = 0; r < 4; r++) {
            int idx = tid + r * 256;          // 1024 float4 over 32x128
            int row = idx >> 5, c4 = (idx & 31) << 2;
            float4 v = *(const float4*)(Bp + (size_t)(k0 + row) * N + n0 + c4);
            uint4 u = make_uint4(f2tf(v.x), f2tf(v.y), f2tf(v.z), f2tf(v.w));
            *(uint4*)&Bs[row][c4] = u;
        }
        __syncthreads();
        #pragma unroll
        for (int kk = 0; kk < 4; kk++) {
            int kb = kk * 8 + lr;
            uint32_t af[4][4], bf[4][2];
            #pragma unroll
            for (int mi = 0; mi < 4; mi++) {
                int m = wy * 64 + mi * 16 + lq;
                af[mi][0] = __float_as_uint(As[m][kb]);
                af[mi][1] = __float_as_uint(As[m + 8][kb]);
                af[mi][2] = __float_as_uint(As[m][kb + 4]);
                af[mi][3] = __float_as_uint(As[m + 8][kb + 4]);
            }
            #pragma unroll
            for (int nj = 0; nj < 4; nj++) {
                int n = wx * 32 + nj * 8 + lq;
                bf[nj][0] = __float_as_uint(Bs[kb][n]);
                bf[nj][1] = __float_as_uint(Bs[kb + 4][n]);
            }
            #pragma unroll
            for (int mi = 0; mi < 4; mi++)
                #pragma unroll
                for (int nj = 0; nj < 4; nj++)
                    mma_tf32(acc[mi][nj], af[mi], bf[nj]);
        }
        __syncthreads();
    }

    #pragma unroll
    for (int mi = 0; mi < 4; mi++) {
        #pragma unroll
        for (int nj = 0; nj < 4; nj++) {
            int m = m0 + wy * 64 + mi * 16 + lq;
            int col = n0 + wx * 32 + nj * 8 + (lr << 1);
            float2 v0 = make_float2(acc[mi][nj][0], acc[mi][nj][1]);
            float2 v1 = make_float2(acc[mi][nj][2], acc[mi][nj][3]);
            if (EPI) {
                float b0 = bias[m], b1 = bias[m + 8];
                float2 r0 = *(const float2*)(Rp + (size_t)m * N + col);
                float2 r1 = *(const float2*)(Rp + (size_t)(m + 8) * N + col);
                v0.x += b0 + r0.x; v0.y += b0 + r0.y;
                v1.x += b1 + r1.x; v1.y += b1 + r1.y;
            }
            *(float2*)(Cp + (size_t)m * N + col) = v0;
            *(float2*)(Cp + (size_t)(m + 8) * N + col) = v1;
        }
    }
}

// ---------------------------------------------------------------------------
// tf32 MMA flash attention. CTA = (q-tile 128, b*head). d=32, S=1024.
// Warp w owns q rows [16w, 16w+16): softmax entirely warp-local.
// P staged through warp-private SMEM rows (syncwarp only).
// ---------------------------------------------------------------------------
#define SMEM_FLOATS (3 * 32 * 132 + 128 * 132)
#define SMEM_BYTES  (SMEM_FLOATS * 4)

__global__ __launch_bounds__(256) void attn_tf32(
    const float* __restrict__ qkv_q, const float* __restrict__ qkv_kv,
    float* __restrict__ outb) {
    int qt = blockIdx.x;
    int bh = blockIdx.y;
    int b = bh >> 3, h = bh & 7;
    size_t base = (size_t)b * 3 * CC * SSZ + (size_t)h * 96 * SSZ;
    const float* Qg = qkv_q  + base;
    const float* Kg = qkv_kv + base + 32 * SSZ;
    const float* Vg = qkv_kv + base + 64 * SSZ;

    extern __shared__ __align__(16) float sm[];
    float* Qs = sm;                 // [32][132] tf32
    float* Ks = Qs + 32 * 132;      // [32][132] tf32
    float* Vs = Ks + 32 * 132;      // [32][132] tf32
    float* Ps = Vs + 32 * 132;      // [128][132] tf32 P / fp32 O-transpose

    int tid = threadIdx.x;
    int lane = tid & 31, wid = tid >> 5;
    int lq = lane >> 2, lr = lane & 3;
    int q0 = qt * 128;
    int r0g = wid * 16 + lq;        // this thread's first global-local q row
    const float scl = 0.0625f;      // 1/sqrt(256)

    // Load Q tile (32 x 128), converting to tf32
    #pragma unroll
    for (int r = 0; r < 4; r++) {
        int idx = tid + r * 256;
        int row = idx >> 5, c4 = (idx & 31) << 2;
        float4 v = *(const float4*)(Qg + (size_t)row * SSZ + q0 + c4);
        uint4 u = make_uint4(f2tf(v.x), f2tf(v.y), f2tf(v.z), f2tf(v.w));
        *(uint4*)&Qs[row * 132 + c4] = u;
    }

    float m0r = -1e30f, m1r = -1e30f, l0 = 0.f, l1 = 0.f;
    float oacc[4][4];
    #pragma unroll
    for (int j = 0; j < 4; j++)
        #pragma unroll
        for (int c = 0; c < 4; c++) oacc[j][c] = 0.f;

    for (int kt = 0; kt < 8; kt++) {
        int k0c = kt * 128;
        __syncthreads();
        #pragma unroll
        for (int r = 0; r < 4; r++) {
            int idx = tid + r * 256;
            int row = idx >> 5, c4 = (idx & 31) << 2;
            float4 kv = *(const float4*)(Kg + (size_t)row * SSZ + k0c + c4);
            float4 vv = *(const float4*)(Vg + (size_t)row * SSZ + k0c + c4);
            *(uint4*)&Ks[row * 132 + c4] =
                make_uint4(f2tf(kv.x), f2tf(kv.y), f2tf(kv.z), f2tf(kv.w));
            *(uint4*)&Vs[row * 132 + c4] =
                make_uint4(f2tf(vv.x), f2tf(vv.y), f2tf(vv.z), f2tf(vv.w));
        }
        __syncthreads();

        // S = Q^T K : m=q(16 rows/warp), n=kpos(128), k=d(32)
        float sacc[16][4];
        #pragma unroll
        for (int nj = 0; nj < 16; nj++)
            #pragma unroll
            for (int c = 0; c < 4; c++) sacc[nj][c] = 0.f;
        #pragma unroll
        for (int kk = 0; kk < 4; kk++) {
            int kb = kk * 8 + lr;
            uint32_t af[4];
            af[0] = __float_as_uint(Qs[kb * 132 + r0g]);
            af[1] = __float_as_uint(Qs[kb * 132 + r0g + 8]);
            af[2] = __float_as_uint(Qs[(kb + 4) * 132 + r0g]);
            af[3] = __float_as_uint(Qs[(kb + 4) * 132 + r0g + 8]);
            #pragma unroll
            for (int nj = 0; nj < 16; nj++) {
                uint32_t bf[2];
                bf[0] = __float_as_uint(Ks[kb * 132 + nj * 8 + lq]);
                bf[1] = __float_as_uint(Ks[(kb + 4) * 132 + nj * 8 + lq]);
                mma_tf32(sacc[nj], af, bf);
            }
        }

        // Online softmax (warp-local; rows r0g and r0g+8)
        float mx0 = -1e30f, mx1 = -1e30f;
        #pragma unroll
        for (int nj = 0; nj < 16; nj++) {
            mx0 = fmaxf(mx0, fmaxf(sacc[nj][0], sacc[nj][1]));
            mx1 = fmaxf(mx1, fmaxf(sacc[nj][2], sacc[nj][3]));
        }
        mx0 *= scl; mx1 *= scl;
        #pragma unroll
        for (int o = 1; o < 4; o <<= 1) {
            mx0 = fmaxf(mx0, __shfl_xor_sync(0xffffffffu, mx0, o));
            mx1 = fmaxf(mx1, __shfl_xor_sync(0xffffffffu, mx1, o));
        }
        float mn0 = fmaxf(m0r, mx0), mn1 = fmaxf(m1r, mx1);
        float al0 = __expf(m0r - mn0), al1 = __expf(m1r - mn1);
        float s0 = 0.f, s1 = 0.f;
        #pragma unroll
        for (int nj = 0; nj < 16; nj++) {
            float p0 = __expf(sacc[nj][0] * scl - mn0);
            float p1 = __expf(sacc[nj][1] * scl - mn0);
            float p2 = __expf(sacc[nj][2] * scl - mn1);
            float p3 = __expf(sacc[nj][3] * scl - mn1);
            s0 += p0 + p1; s1 += p2 + p3;
            int col = nj * 8 + (lr << 1);
            *(float2*)&Ps[r0g * 132 + col] = make_float2(
                __uint_as_float(f2tf(p0)), __uint_as_float(f2tf(p1)));
            *(float2*)&Ps[(r0g + 8) * 132 + col] = make_float2(
                __uint_as_float(f2tf(p2)), __uint_as_float(f2tf(p3)));
        }
        #pragma unroll
        for (int o = 1; o < 4; o <<= 1) {
            s0 += __shfl_xor_sync(0xffffffffu, s0, o);
            s1 += __shfl_xor_sync(0xffffffffu, s1, o);
        }
        l0 = l0 * al0 + s0; l1 = l1 * al1 + s1;
        m0r = mn0; m1r = mn1;
        #pragma unroll
        for (int nj = 0; nj < 4; nj++) {
            oacc[nj][0] *= al0; oacc[nj][1] *= al0;
            oacc[nj][2] *= al1; oacc[nj][3] *= al1;
        }
        __syncwarp();

        // O += P V^T : m=q(16), n=d(32), k=kpos(128)
        #pragma unroll
        for (int kk = 0; kk < 16; kk++) {
            int kb = kk * 8 + lr;
            uint32_t af[4];
            af[0] = __float_as_uint(Ps[r0g * 132 + kb]);
            af[1] = __float_as_uint(Ps[(r0g + 8) * 132 + kb]);
            af[2] = __float_as_uint(Ps[r0g * 132 + kb + 4]);
            af[3] = __float_as_uint(Ps[(r0g + 8) * 132 + kb + 4]);
            #pragma unroll
            for (int nj = 0; nj < 4; nj++) {
                uint32_t bf[2];
                bf[0] = __float_as_uint(Vs[(nj * 8 + lq) * 132 + kb]);
                bf[1] = __float_as_uint(Vs[(nj * 8 + lq) * 132 + kb + 4]);
                mma_tf32(oacc[nj], af, bf);
            }
        }
        __syncwarp();
    }

    // Normalize + transpose to [d][q] in SMEM, then coalesced global store.
    float il0 = 1.f / l0, il1 = 1.f / l1;
    __syncthreads();
    #pragma unroll
    for (int nj = 0; nj < 4; nj++) {
        int d0 = nj * 8 + (lr << 1);
        Ps[d0 * 132 + r0g]           = oacc[nj][0] * il0;
        Ps[(d0 + 1) * 132 + r0g]     = oacc[nj][1] * il0;
        Ps[d0 * 132 + r0g + 8]       = oacc[nj][2] * il1;
        Ps[(d0 + 1) * 132 + r0g + 8] = oacc[nj][3] * il1;
    }
    __syncthreads();
    #pragma unroll
    for (int r = 0; r < 4; r++) {
        int idx = tid + r * 256;      // 1024 float4 over 32 x 128
        int row = idx >> 5, c4 = (idx & 31) << 2;
        *(float4*)(outb + ((size_t)b * CC + h * 32 + row) * SSZ + q0 + c4) =
            *(float4*)&Ps[row * 132 + c4];
    }
}

// ---------------------------------------------------------------------------
extern "C" void kernel_launch(void* const* d_in, const int* in_sizes, int n_in,
                              void* d_out, int out_size) {
    const float* xA    = (const float*)d_in[0];
    const float* xB    = (const float*)d_in[1];
    const float* gA    = (const float*)d_in[2];
    const float* bA    = (const float*)d_in[3];
    const float* gB    = (const float*)d_in[4];
    const float* bB    = (const float*)d_in[5];
    const float* WqkvA = (const float*)d_in[6];
    const float* WqkvB = (const float*)d_in[7];
    const float* WoutA = (const float*)d_in[8];
    const float* boutA = (const float*)d_in[9];
    const float* WoutB = (const float*)d_in[10];
    const float* boutB = (const float*)d_in[11];
    float* out = (float*)d_out;

    void *pn, *pq, *pa;
    cudaGetSymbolAddress(&pn, g_norm);
    cudaGetSymbolAddress(&pq, g_qkv);
    cudaGetSymbolAddress(&pa, g_attn);
    float* normA = (float*)pn;
    float* normB = normA + (size_t)BSZ * CC * SSZ;
    float* qkvA  = (float*)pq;
    float* qkvB  = qkvA + (size_t)BSZ * 3 * CC * SSZ;
    float* attnA = (float*)pa;
    float* attnB = attnA + (size_t)BSZ * CC * SSZ;

    const long CS = (long)CC * SSZ;
    const long Q3 = (long)3 * CC * SSZ;

    // 1) GroupNorm
    groupnorm_kernel<<<BSZ * NG, 256>>>(xA, gA, bA, normA);
    groupnorm_kernel<<<BSZ * NG, 256>>>(xB, gB, bB, normB);

    // 2) QKV projections (768 x 256) x (256 x 1024), tf32 MMA
    dim3 gq(8, 6, BSZ);
    gemm_tf32<false><<<gq, 256>>>(WqkvA, normA, qkvA, nullptr, nullptr, CS, Q3, 0);
    gemm_tf32<false><<<gq, 256>>>(WqkvB, normB, qkvB, nullptr, nullptr, CS, Q3, 0);

    // 3) Cross attention (tf32 MMA flash)
    cudaFuncSetAttribute(attn_tf32,
                         cudaFuncAttributeMaxDynamicSharedMemorySize, SMEM_BYTES);
    dim3 ga(8, BSZ * NHD);
    attn_tf32<<<ga, 256, SMEM_BYTES>>>(qkvB, qkvA, attnA);
    attn_tf32<<<ga, 256, SMEM_BYTES>>>(qkvA, qkvB, attnB);

    // 4) Output projection + bias + residual(norm)
    dim3 gp(8, 2, BSZ);
    gemm_tf32<true><<<gp, 256>>>(WoutA, attnA, out, boutA, normA, CS, CS, CS);
    gemm_tf32<true><<<gp, 256>>>(WoutB, attnB, out + (size_t)BSZ * CC * SSZ,
                                 boutB, normB, CS, CS, CS);
}

// round 3
// speedup vs baseline: 4.7627x; 2.1042x over previous
#include <cuda_runtime.h>
#include <cuda_bf16.h>
#include <math.h>
#include <stdint.h>

#define BSZ 16
#define CC  256
#define SSZ 1024
#define NHD 8
#define NG  16
#define CPG 16
#define EPSV 1e-5f

__device__ __align__(128) float g_norm[2 * BSZ * CC * SSZ];
__device__ __align__(128) float g_qkv [2 * BSZ * 3 * CC * SSZ];
__device__ __align__(128) float g_attn[2 * BSZ * CC * SSZ];

__device__ __forceinline__ uint32_t packbf(float lo, float hi) {
    __nv_bfloat162 h = __floats2bfloat162_rn(lo, hi);
    return *(uint32_t*)&h;
}
__device__ __forceinline__ void mma_bf16(float d[4], const uint32_t a[4],
                                         const uint32_t b[2]) {
    asm volatile(
        "mma.sync.aligned.m16n8k16.row.col.f32.bf16.bf16.f32 "
        "{%0,%1,%2,%3}, {%4,%5,%6,%7}, {%8,%9}, {%0,%1,%2,%3};\n"
        : "+f"(d[0]), "+f"(d[1]), "+f"(d[2]), "+f"(d[3])
        : "r"(a[0]), "r"(a[1]), "r"(a[2]), "r"(a[3]), "r"(b[0]), "r"(b[1]));
}

// ---------------------------------------------------------------------------
// GroupNorm (memory bound)
// ---------------------------------------------------------------------------
__global__ void groupnorm_kernel(const float* __restrict__ x,
                                 const float* __restrict__ gamma,
                                 const float* __restrict__ beta,
                                 float* __restrict__ out) {
    int bg = blockIdx.x;
    int b = bg / NG, g = bg % NG;
    const int n = CPG * SSZ;
    const float* xp = x + (size_t)(b * CC + g * CPG) * SSZ;
    float* op = out + (size_t)(b * CC + g * CPG) * SSZ;
    int tid = threadIdx.x;

    const float4* x4 = (const float4*)xp;
    float s = 0.f, s2 = 0.f;
    #pragma unroll 4
    for (int i = tid; i < n / 4; i += 256) {
        float4 v = x4[i];
        s  += v.x + v.y + v.z + v.w;
        s2 += v.x * v.x + v.y * v.y + v.z * v.z + v.w * v.w;
    }
    __shared__ float rs[256], rs2[256];
    rs[tid] = s; rs2[tid] = s2;
    __syncthreads();
    for (int o = 128; o > 0; o >>= 1) {
        if (tid < o) { rs[tid] += rs[tid + o]; rs2[tid] += rs2[tid + o]; }
        __syncthreads();
    }
    float mu = rs[0] / (float)n;
    float var = rs2[0] / (float)n - mu * mu;
    float rstd = rsqrtf(var + EPSV);

    float4* o4 = (float4*)op;
    for (int i = tid; i < n / 4; i += 256) {
        int c = g * CPG + (i >> 8);
        float sc = gamma[c] * rstd;
        float sh = beta[c] - mu * sc;
        float4 v = x4[i];
        float4 r;
        r.x = v.x * sc + sh; r.y = v.y * sc + sh;
        r.z = v.z * sc + sh; r.w = v.w * sc + sh;
        o4[i] = r;
    }
}

// ---------------------------------------------------------------------------
// bf16 MMA GEMM: C[M x 1024] = A[M x 256] * B[256 x 1024] (+bias+residual)
// CTA 128x128, BK=32, 8 warps at 64x32, m16n8k16.
// As: [m=128][kpair] stride 20 (CF for frag LDS); Bs: [kpair][n=128] stride 136.
// ---------------------------------------------------------------------------
template <bool EPI>
__global__ __launch_bounds__(256) void gemm_bf16(
    const float* __restrict__ A, const float* __restrict__ Bm,
    float* __restrict__ Cm, const float* __restrict__ bias,
    const float* __restrict__ res, long strideB, long strideC, long strideR) {
    const int K = 256, N = 1024;
    int bz = blockIdx.z;
    const float* Bp = Bm + (size_t)bz * strideB;
    float* Cp = Cm + (size_t)bz * strideC;
    const float* Rp = EPI ? (res + (size_t)bz * strideR) : nullptr;
    int m0 = blockIdx.y * 128, n0 = blockIdx.x * 128;

    __shared__ __align__(16) uint32_t As[128 * 20];   // [m][kpair] stride 20
    __shared__ __align__(16) uint32_t Bs[16 * 136];   // [kpair][n] stride 136

    int tid = threadIdx.x;
    int lane = tid & 31, wid = tid >> 5;
    int wy = wid >> 2, wx = wid & 3;
    int lq = lane >> 2, lr = lane & 3;

    float acc[4][4][4];
    #pragma unroll
    for (int i = 0; i < 4; i++)
        #pragma unroll
        for (int j = 0; j < 4; j++)
            #pragma unroll
            for (int c = 0; c < 4; c++) acc[i][j][c] = 0.f;

    for (int k0 = 0; k0 < K; k0 += 32) {
        // Stage A (128 x 32): coalesced float4, pack pairs along k
        #pragma unroll
        for (int r = 0; r < 4; r++) {
            int idx = tid + r * 256;
            int row = idx >> 3, c4 = idx & 7;
            float4 v = *(const float4*)(A + (size_t)(m0 + row) * K + k0 + c4 * 4);
            uint2 u = make_uint2(packbf(v.x, v.y), packbf(v.z, v.w));
            *(uint2*)&As[row * 20 + c4 * 2] = u;
        }
        // Stage B (32 x 128): rows 2kp,2kp+1 interleaved into bf16x2 pairs
        #pragma unroll
        for (int r = 0; r < 2; r++) {
            int idx = tid + r * 256;
            int kp = idx >> 5, n4 = idx & 31;
            const float* b0p = Bp + (size_t)(k0 + 2 * kp) * N + n0 + n4 * 4;
            float4 v0 = *(const float4*)b0p;
            float4 v1 = *(const float4*)(b0p + N);
            uint4 u = make_uint4(packbf(v0.x, v1.x), packbf(v0.y, v1.y),
                                 packbf(v0.z, v1.z), packbf(v0.w, v1.w));
            *(uint4*)&Bs[kp * 136 + n4 * 4] = u;
        }
        __syncthreads();
        #pragma unroll
        for (int kk = 0; kk < 2; kk++) {
            int p0 = kk * 8 + lr;
            uint32_t af[4][4], bf[4][2];
            #pragma unroll
            for (int mi = 0; mi < 4; mi++) {
                int m = wy * 64 + mi * 16 + lq;
                af[mi][0] = As[m * 20 + p0];
                af[mi][1] = As[(m + 8) * 20 + p0];
                af[mi][2] = As[m * 20 + p0 + 4];
                af[mi][3] = As[(m + 8) * 20 + p0 + 4];
            }
            #pragma unroll
            for (int nj = 0; nj < 4; nj++) {
                int n = wx * 32 + nj * 8 + lq;
                bf[nj][0] = Bs[p0 * 136 + n];
                bf[nj][1] = Bs[(p0 + 4) * 136 + n];
            }
            #pragma unroll
            for (int mi = 0; mi < 4; mi++)
                #pragma unroll
                for (int nj = 0; nj < 4; nj++)
                    mma_bf16(acc[mi][nj], af[mi], bf[nj]);
        }
        __syncthreads();
    }

    #pragma unroll
    for (int mi = 0; mi < 4; mi++) {
        #pragma unroll
        for (int nj = 0; nj < 4; nj++) {
            int m = m0 + wy * 64 + mi * 16 + lq;
            int col = n0 + wx * 32 + nj * 8 + (lr << 1);
            float2 v0 = make_float2(acc[mi][nj][0], acc[mi][nj][1]);
            float2 v1 = make_float2(acc[mi][nj][2], acc[mi][nj][3]);
            if (EPI) {
                float b0 = bias[m], b1 = bias[m + 8];
                float2 r0 = *(const float2*)(Rp + (size_t)m * N + col);
                float2 r1 = *(const float2*)(Rp + (size_t)(m + 8) * N + col);
                v0.x += b0 + r0.x; v0.y += b0 + r0.y;
                v1.x += b1 + r1.x; v1.y += b1 + r1.y;
            }
            *(float2*)(Cp + (size_t)m * N + col) = v0;
            *(float2*)(Cp + (size_t)(m + 8) * N + col) = v1;
        }
    }
}

// ---------------------------------------------------------------------------
// bf16 MMA flash attention. CTA = (q-tile 128, b*head). d=32, S=1024.
// Warp owns 16 q rows (softmax warp-local). P stays in registers:
// S-GEMM C-frag pairs == O-GEMM A-frag pairs.
// Qs/Ks: [dpair=16][x=128] stride 136; Vs: [d=32][kpair=64] stride 68.
// ---------------------------------------------------------------------------
__global__ __launch_bounds__(256) void attn_bf16(
    const float* __restrict__ qkv_q, const float* __restrict__ qkv_kv,
    float* __restrict__ outb) {
    __shared__ __align__(16) union SM {
        struct { uint32_t Qs[16 * 136]; uint32_t Ks[16 * 136]; uint32_t Vs[32 * 68]; } s;
        float Ot[32 * 132];
    } sm;

    int qt = blockIdx.x;
    int bh = blockIdx.y;
    int b = bh >> 3, h = bh & 7;
    size_t base = (size_t)b * 3 * CC * SSZ + (size_t)h * 96 * SSZ;
    const float* Qg = qkv_q  + base;
    const float* Kg = qkv_kv + base + 32 * SSZ;
    const float* Vg = qkv_kv + base + 64 * SSZ;

    int tid = threadIdx.x;
    int lane = tid & 31, wid = tid >> 5;
    int lq = lane >> 2, lr = lane & 3;
    int q0 = qt * 128;
    int r0g = wid * 16 + lq;           // this thread's first q row
    const float scl = 0.0625f;         // 1/sqrt(256)

    // Stage Q (32d x 128q) as [dpair][q], bf16x2 pairs along d
    #pragma unroll
    for (int r = 0; r < 2; r++) {
        int idx = tid + r * 256;
        int dp = idx >> 5, q4 = idx & 31;
        const float* p0 = Qg + (size_t)(2 * dp) * SSZ + q0 + q4 * 4;
        float4 v0 = *(const float4*)p0;
        float4 v1 = *(const float4*)(p0 + SSZ);
        uint4 u = make_uint4(packbf(v0.x, v1.x), packbf(v0.y, v1.y),
                             packbf(v0.z, v1.z), packbf(v0.w, v1.w));
        *(uint4*)&sm.s.Qs[dp * 136 + q4 * 4] = u;
    }

    float m0r = -1e30f, m1r = -1e30f, l0 = 0.f, l1 = 0.f;
    float oacc[4][4];
    #pragma unroll
    for (int j = 0; j < 4; j++)
        #pragma unroll
        for (int c = 0; c < 4; c++) oacc[j][c] = 0.f;

    for (int kt = 0; kt < 8; kt++) {
        int k0c = kt * 128;
        __syncthreads();
        // Stage K tile (32d x 128) as [dpair][kpos]
        #pragma unroll
        for (int r = 0; r < 2; r++) {
            int idx = tid + r * 256;
            int dp = idx >> 5, n4 = idx & 31;
            const float* p0 = Kg + (size_t)(2 * dp) * SSZ + k0c + n4 * 4;
            float4 v0 = *(const float4*)p0;
            float4 v1 = *(const float4*)(p0 + SSZ);
            uint4 u = make_uint4(packbf(v0.x, v1.x), packbf(v0.y, v1.y),
                                 packbf(v0.z, v1.z), packbf(v0.w, v1.w));
            *(uint4*)&sm.s.Ks[dp * 136 + n4 * 4] = u;
        }
        // Stage V tile (32d x 128) as [d][kpair], pairs along kpos
        #pragma unroll
        for (int r = 0; r < 4; r++) {
            int idx = tid + r * 256;
            int d = idx >> 5, j4 = idx & 31;
            float4 v = *(const float4*)(Vg + (size_t)d * SSZ + k0c + j4 * 4);
            uint2 u = make_uint2(packbf(v.x, v.y), packbf(v.z, v.w));
            *(uint2*)&sm.s.Vs[d * 68 + j4 * 2] = u;
        }
        __syncthreads();

        // S = Q^T K : m=16 q rows/warp, n=128 kpos, k=d(32) -> 2 k16 chunks
        float sacc[16][4];
        #pragma unroll
        for (int nj = 0; nj < 16; nj++)
            #pragma unroll
            for (int c = 0; c < 4; c++) sacc[nj][c] = 0.f;
        #pragma unroll
        for (int kk = 0; kk < 2; kk++) {
            int p0 = kk * 8 + lr;
            uint32_t af[4];
            af[0] = sm.s.Qs[p0 * 136 + r0g];
            af[1] = sm.s.Qs[p0 * 136 + r0g + 8];
            af[2] = sm.s.Qs[(p0 + 4) * 136 + r0g];
            af[3] = sm.s.Qs[(p0 + 4) * 136 + r0g + 8];
            #pragma unroll
            for (int nj = 0; nj < 16; nj++) {
                uint32_t bf[2];
                bf[0] = sm.s.Ks[p0 * 136 + nj * 8 + lq];
                bf[1] = sm.s.Ks[(p0 + 4) * 136 + nj * 8 + lq];
                mma_bf16(sacc[nj], af, bf);
            }
        }

        // Online softmax (warp-local rows r0g, r0g+8)
        float mx0 = -1e30f, mx1 = -1e30f;
        #pragma unroll
        for (int nj = 0; nj < 16; nj++) {
            mx0 = fmaxf(mx0, fmaxf(sacc[nj][0], sacc[nj][1]));
            mx1 = fmaxf(mx1, fmaxf(sacc[nj][2], sacc[nj][3]));
        }
        mx0 *= scl; mx1 *= scl;
        #pragma unroll
        for (int o = 1; o < 4; o <<= 1) {
            mx0 = fmaxf(mx0, __shfl_xor_sync(0xffffffffu, mx0, o));
            mx1 = fmaxf(mx1, __shfl_xor_sync(0xffffffffu, mx1, o));
        }
        float mn0 = fmaxf(m0r, mx0), mn1 = fmaxf(m1r, mx1);
        float al0 = __expf(m0r - mn0), al1 = __expf(m1r - mn1);
        float s0 = 0.f, s1 = 0.f;
        #pragma unroll
        for (int nj = 0; nj < 16; nj++) {
            float p0f = __expf(sacc[nj][0] * scl - mn0);
            float p1f = __expf(sacc[nj][1] * scl - mn0);
            float p2f = __expf(sacc[nj][2] * scl - mn1);
            float p3f = __expf(sacc[nj][3] * scl - mn1);
            s0 += p0f + p1f; s1 += p2f + p3f;
            sacc[nj][0] = p0f; sacc[nj][1] = p1f;
            sacc[nj][2] = p2f; sacc[nj][3] = p3f;
        }
        #pragma unroll
        for (int o = 1; o < 4; o <<= 1) {
            s0 += __shfl_xor_sync(0xffffffffu, s0, o);
            s1 += __shfl_xor_sync(0xffffffffu, s1, o);
        }
        l0 = l0 * al0 + s0; l1 = l1 * al1 + s1;
        m0r = mn0; m1r = mn1;
        #pragma unroll
        for (int nj = 0; nj < 4; nj++) {
            oacc[nj][0] *= al0; oacc[nj][1] *= al0;
            oacc[nj][2] *= al1; oacc[nj][3] *= al1;
        }

        // O += P V^T : m=16 q, n=32 d, k=128 kpos. P from registers:
        // S C-frag (rows lq/lq+8, cols 2lr/2lr+1 of tile nj) packs directly
        // into O A-frag pairs for k16 chunk kk via nj = 2kk, 2kk+1.
        #pragma unroll
        for (int kk = 0; kk < 8; kk++) {
            uint32_t af[4];
            af[0] = packbf(sacc[2 * kk][0],     sacc[2 * kk][1]);
            af[1] = packbf(sacc[2 * kk][2],     sacc[2 * kk][3]);
            af[2] = packbf(sacc[2 * kk + 1][0], sacc[2 * kk + 1][1]);
            af[3] = packbf(sacc[2 * kk + 1][2], sacc[2 * kk + 1][3]);
            int p0 = kk * 8 + lr;
            #pragma unroll
            for (int nj = 0; nj < 4; nj++) {
                uint32_t bf[2];
                bf[0] = sm.s.Vs[(nj * 8 + lq) * 68 + p0];
                bf[1] = sm.s.Vs[(nj * 8 + lq) * 68 + p0 + 4];
                mma_bf16(oacc[nj], af, bf);
            }
        }
    }

    // Normalize + transpose to [d][q] (SMEM reuse), then coalesced store.
    float il0 = 1.f / l0, il1 = 1.f / l1;
    __syncthreads();
    #pragma unroll
    for (int nj = 0; nj < 4; nj++) {
        int d0 = nj * 8 + (lr << 1);
        sm.Ot[d0 * 132 + r0g]           = oacc[nj][0] * il0;
        sm.Ot[(d0 + 1) * 132 + r0g]     = oacc[nj][1] * il0;
        sm.Ot[d0 * 132 + r0g + 8]       = oacc[nj][2] * il1;
        sm.Ot[(d0 + 1) * 132 + r0g + 8] = oacc[nj][3] * il1;
    }
    __syncthreads();
    #pragma unroll
    for (int r = 0; r < 4; r++) {
        int idx = tid + r * 256;
        int row = idx >> 5, c4 = (idx & 31) << 2;
        *(float4*)(outb + ((size_t)b * CC + h * 32 + row) * SSZ + q0 + c4) =
            *(float4*)&sm.Ot[row * 132 + c4];
    }
}

// ---------------------------------------------------------------------------
extern "C" void kernel_launch(void* const* d_in, const int* in_sizes, int n_in,
                              void* d_out, int out_size) {
    const float* xA    = (const float*)d_in[0];
    const float* xB    = (const float*)d_in[1];
    const float* gA    = (const float*)d_in[2];
    const float* bA    = (const float*)d_in[3];
    const float* gB    = (const float*)d_in[4];
    const float* bB    = (const float*)d_in[5];
    const float* WqkvA = (const float*)d_in[6];
    const float* WqkvB = (const float*)d_in[7];
    const float* WoutA = (const float*)d_in[8];
    const float* boutA = (const float*)d_in[9];
    const float* WoutB = (const float*)d_in[10];
    const float* boutB = (const float*)d_in[11];
    float* out = (float*)d_out;

    void *pn, *pq, *pa;
    cudaGetSymbolAddress(&pn, g_norm);
    cudaGetSymbolAddress(&pq, g_qkv);
    cudaGetSymbolAddress(&pa, g_attn);
    float* normA = (float*)pn;
    float* normB = normA + (size_t)BSZ * CC * SSZ;
    float* qkvA  = (float*)pq;
    float* qkvB  = qkvA + (size_t)BSZ * 3 * CC * SSZ;
    float* attnA = (float*)pa;
    float* attnB = attnA + (size_t)BSZ * CC * SSZ;

    const long CS = (long)CC * SSZ;
    const long Q3 = (long)3 * CC * SSZ;

    groupnorm_kernel<<<BSZ * NG, 256>>>(xA, gA, bA, normA);
    groupnorm_kernel<<<BSZ * NG, 256>>>(xB, gB, bB, normB);

    dim3 gq(8, 6, BSZ);
    gemm_bf16<false><<<gq, 256>>>(WqkvA, normA, qkvA, nullptr, nullptr, CS, Q3, 0);
    gemm_bf16<false><<<gq, 256>>>(WqkvB, normB, qkvB, nullptr, nullptr, CS, Q3, 0);

    dim3 ga(8, BSZ * NHD);
    attn_bf16<<<ga, 256>>>(qkvB, qkvA, attnA);
    attn_bf16<<<ga, 256>>>(qkvA, qkvB, attnB);

    dim3 gp(8, 2, BSZ);
    gemm_bf16<true><<<gp, 256>>>(WoutA, attnA, out, boutA, normA, CS, CS, CS);
    gemm_bf16<true><<<gp, 256>>>(WoutB, attnB, out + (size_t)BSZ * CC * SSZ,
                                 boutB, normB, CS, CS, CS);
}

// round 5
// speedup vs baseline: 4.9938x; 1.0485x over previous
#include <cuda_runtime.h>
#include <cuda_bf16.h>
#include <math.h>
#include <stdint.h>

#define BSZ 16
#define CC  256
#define SSZ 1024
#define NHD 8
#define NG  16
#define CPG 16
#define EPSV 1e-5f

__device__ __align__(128) float g_norm[2 * BSZ * CC * SSZ];
__device__ __align__(128) float g_qkv [2 * BSZ * 3 * CC * SSZ];
__device__ __align__(128) float g_attn[2 * BSZ * CC * SSZ];

__device__ __forceinline__ uint32_t packbf(float lo, float hi) {
    __nv_bfloat162 h = __floats2bfloat162_rn(lo, hi);
    return *(uint32_t*)&h;
}
__device__ __forceinline__ void mma_bf16(float d[4], const uint32_t a[4],
                                         const uint32_t b[2]) {
    asm volatile(
        "mma.sync.aligned.m16n8k16.row.col.f32.bf16.bf16.f32 "
        "{%0,%1,%2,%3}, {%4,%5,%6,%7}, {%8,%9}, {%0,%1,%2,%3};\n"
        : "+f"(d[0]), "+f"(d[1]), "+f"(d[2]), "+f"(d[3])
        : "r"(a[0]), "r"(a[1]), "r"(a[2]), "r"(a[3]), "r"(b[0]), "r"(b[1]));
}
__device__ __forceinline__ void ldmx4(uint32_t r[4], uint32_t addr) {
    asm volatile("ldmatrix.sync.aligned.m8n8.x4.shared.b16 {%0,%1,%2,%3}, [%4];"
                 : "=r"(r[0]), "=r"(r[1]), "=r"(r[2]), "=r"(r[3]) : "r"(addr));
}
__device__ __forceinline__ void ldmx4t(uint32_t r[4], uint32_t addr) {
    asm volatile("ldmatrix.sync.aligned.m8n8.x4.trans.shared.b16 {%0,%1,%2,%3}, [%4];"
                 : "=r"(r[0]), "=r"(r[1]), "=r"(r[2]), "=r"(r[3]) : "r"(addr));
}

// ---------------------------------------------------------------------------
// GroupNorm (memory bound)
// ---------------------------------------------------------------------------
__global__ void groupnorm_kernel(const float* __restrict__ x,
                                 const float* __restrict__ gamma,
                                 const float* __restrict__ beta,
                                 float* __restrict__ out) {
    int bg = blockIdx.x;
    int b = bg / NG, g = bg % NG;
    const int n = CPG * SSZ;
    const float* xp = x + (size_t)(b * CC + g * CPG) * SSZ;
    float* op = out + (size_t)(b * CC + g * CPG) * SSZ;
    int tid = threadIdx.x;

    const float4* x4 = (const float4*)xp;
    float s = 0.f, s2 = 0.f;
    #pragma unroll 4
    for (int i = tid; i < n / 4; i += 256) {
        float4 v = x4[i];
        s  += v.x + v.y + v.z + v.w;
        s2 += v.x * v.x + v.y * v.y + v.z * v.z + v.w * v.w;
    }
    __shared__ float rs[256], rs2[256];
    rs[tid] = s; rs2[tid] = s2;
    __syncthreads();
    for (int o = 128; o > 0; o >>= 1) {
        if (tid < o) { rs[tid] += rs[tid + o]; rs2[tid] += rs2[tid + o]; }
        __syncthreads();
    }
    float mu = rs[0] / (float)n;
    float var = rs2[0] / (float)n - mu * mu;
    float rstd = rsqrtf(var + EPSV);

    float4* o4 = (float4*)op;
    for (int i = tid; i < n / 4; i += 256) {
        int c = g * CPG + (i >> 8);
        float sc = gamma[c] * rstd;
        float sh = beta[c] - mu * sc;
        float4 v = x4[i];
        float4 r;
        r.x = v.x * sc + sh; r.y = v.y * sc + sh;
        r.z = v.z * sc + sh; r.w = v.w * sc + sh;
        o4[i] = r;
    }
}

// ---------------------------------------------------------------------------
// bf16 MMA GEMM, ldmatrix + double-buffered. C = A[Mx256] * B[256x1024].
// As: [m=128][k=32] bf16, row stride 80B. Bs: [k=32][n=128] bf16, stride 272B.
// ---------------------------------------------------------------------------
#define GA_BYTES (128 * 80)
#define GB_BYTES (32 * 272)
#define GBUF (GA_BYTES + GB_BYTES)

template <bool EPI>
__global__ __launch_bounds__(256, 2) void gemm_bf16(
    const float* __restrict__ A, const float* __restrict__ Bm,
    float* __restrict__ Cm, const float* __restrict__ bias,
    const float* __restrict__ res, long strideB, long strideC, long strideR) {
    const int K = 256, N = 1024;
    int bz = blockIdx.z;
    const float* Bp = Bm + (size_t)bz * strideB;
    float* Cp = Cm + (size_t)bz * strideC;
    const float* Rp = EPI ? (res + (size_t)bz * strideR) : nullptr;
    int m0 = blockIdx.y * 128, n0 = blockIdx.x * 128;

    __shared__ __align__(16) uint8_t smem[2 * GBUF];
    uint32_t sbase = (uint32_t)__cvta_generic_to_shared(smem);

    int tid = threadIdx.x;
    int lane = tid & 31, wid = tid >> 5;
    int wy = wid >> 2, wx = wid & 3;
    int lq = lane >> 2, lr = lane & 3;
    int l7 = lane & 7, lb = (lane >> 3) & 1, lhi = lane >> 4;

    float acc[4][4][4];
    #pragma unroll
    for (int i = 0; i < 4; i++)
        #pragma unroll
        for (int j = 0; j < 4; j++)
            #pragma unroll
            for (int c = 0; c < 4; c++) acc[i][j][c] = 0.f;

    // prologue: stage k0=0 into buffer 0
    {
        uint8_t* As = smem;
        uint8_t* Bs = smem + GA_BYTES;
        #pragma unroll
        for (int r = 0; r < 4; r++) {
            int idx = tid + r * 256;
            int row = idx >> 3, c4 = (idx & 7) << 2;     // 128 rows x 8 col-groups
            float4 v = *(const float4*)(A + (size_t)(m0 + row) * K + c4);
            *(uint2*)(As + row * 80 + c4 * 2) =
                make_uint2(packbf(v.x, v.y), packbf(v.z, v.w));
        }
        #pragma unroll
        for (int r = 0; r < 4; r++) {
            int idx = tid + r * 256;
            int krow = idx >> 5, n4 = (idx & 31) << 2;   // 32 rows x 32 col-groups
            float4 v = *(const float4*)(Bp + (size_t)krow * N + n0 + n4);
            *(uint2*)(Bs + krow * 272 + n4 * 2) =
                make_uint2(packbf(v.x, v.y), packbf(v.z, v.w));
        }
    }
    __syncthreads();

    #pragma unroll
    for (int it = 0; it < 8; it++) {
        uint32_t sA = sbase + (it & 1) * GBUF;
        uint32_t sB = sA + GA_BYTES;
        // load + cvt next tile into registers
        uint2 sa[4], sb[4];
        if (it < 7) {
            int k0 = (it + 1) * 32;
            #pragma unroll
            for (int r = 0; r < 4; r++) {
                int idx = tid + r * 256;
                int row = idx >> 3, c4 = (idx & 7) << 2;
                float4 v = *(const float4*)(A + (size_t)(m0 + row) * K + k0 + c4);
                sa[r] = make_uint2(packbf(v.x, v.y), packbf(v.z, v.w));
            }
            #pragma unroll
            for (int r = 0; r < 4; r++) {
                int idx = tid + r * 256;
                int krow = idx >> 5, n4 = (idx & 31) << 2;
                float4 v = *(const float4*)(Bp + (size_t)(k0 + krow) * N + n0 + n4);
                sb[r] = make_uint2(packbf(v.x, v.y), packbf(v.z, v.w));
            }
        }
        // compute current
        #pragma unroll
        for (int kk = 0; kk < 2; kk++) {
            uint32_t af[4][4], bf[2][4];
            #pragma unroll
            for (int mi = 0; mi < 4; mi++) {
                int row = wy * 64 + mi * 16 + l7 + lb * 8;
                int col = kk * 16 + lhi * 8;
                ldmx4(af[mi], sA + row * 80 + col * 2);
            }
            #pragma unroll
            for (int njp = 0; njp < 2; njp++) {
                int row = kk * 16 + l7 + lb * 8;
                int col = wx * 32 + njp * 16 + lhi * 8;
                ldmx4t(bf[njp], sB + row * 272 + col * 2);
            }
            #pragma unroll
            for (int mi = 0; mi < 4; mi++)
                #pragma unroll
                for (int njp = 0; njp < 2; njp++) {
                    mma_bf16(acc[mi][njp * 2],     af[mi], &bf[njp][0]);
                    mma_bf16(acc[mi][njp * 2 + 1], af[mi], &bf[njp][2]);
                }
        }
        // store next tile
        if (it < 7) {
            uint8_t* As = smem + ((it + 1) & 1) * GBUF;
            uint8_t* Bs = As + GA_BYTES;
            #pragma unroll
            for (int r = 0; r < 4; r++) {
                int idx = tid + r * 256;
                int row = idx >> 3, c4 = (idx & 7) << 2;
                *(uint2*)(As + row * 80 + c4 * 2) = sa[r];
            }
            #pragma unroll
            for (int r = 0; r < 4; r++) {
                int idx = tid + r * 256;
                int krow = idx >> 5, n4 = (idx & 31) << 2;
                *(uint2*)(Bs + krow * 272 + n4 * 2) = sb[r];
            }
            __syncthreads();
        }
    }

    #pragma unroll
    for (int mi = 0; mi < 4; mi++) {
        #pragma unroll
        for (int nj = 0; nj < 4; nj++) {
            int m = m0 + wy * 64 + mi * 16 + lq;
            int col = n0 + wx * 32 + nj * 8 + (lr << 1);
            float2 v0 = make_float2(acc[mi][nj][0], acc[mi][nj][1]);
            float2 v1 = make_float2(acc[mi][nj][2], acc[mi][nj][3]);
            if (EPI) {
                float b0 = bias[m], b1 = bias[m + 8];
                float2 r0 = *(const float2*)(Rp + (size_t)m * N + col);
                float2 r1 = *(const float2*)(Rp + (size_t)(m + 8) * N + col);
                v0.x += b0 + r0.x; v0.y += b0 + r0.y;
                v1.x += b1 + r1.x; v1.y += b1 + r1.y;
            }
            *(float2*)(Cp + (size_t)m * N + col) = v0;
            *(float2*)(Cp + (size_t)(m + 8) * N + col) = v1;
        }
    }
}

// ---------------------------------------------------------------------------
// bf16 MMA flash attention, ldmatrix edition. CTA = (q-tile 128, b*head).
// Qs/Ks/Vs: [d=32][x=128] bf16, row stride 272B (natural layout, no transpose).
// Q,K frags via ldmatrix.trans; V frags via ldmatrix; P stays in registers.
// ---------------------------------------------------------------------------
#define ATT_TILE (32 * 272)

__global__ __launch_bounds__(256, 2) void attn_bf16(
    const float* __restrict__ qkv_q, const float* __restrict__ qkv_kv,
    float* __restrict__ outb) {
    __shared__ __align__(16) union SM {
        uint8_t raw[3 * ATT_TILE];
        float Ot[32 * 132];
    } sm;
    uint32_t sQ = (uint32_t)__cvta_generic_to_shared(sm.raw);
    uint32_t sK = sQ + ATT_TILE;
    uint32_t sV = sK + ATT_TILE;

    int qt = blockIdx.x;
    int bh = blockIdx.y;
    int b = bh >> 3, h = bh & 7;
    size_t base = (size_t)b * 3 * CC * SSZ + (size_t)h * 96 * SSZ;
    const float* Qg = qkv_q  + base;
    const float* Kg = qkv_kv + base + 32 * SSZ;
    const float* Vg = qkv_kv + base + 64 * SSZ;

    int tid = threadIdx.x;
    int lane = tid & 31, wid = tid >> 5;
    int lq = lane >> 2, lr = lane & 3;
    int l7 = lane & 7, lb = (lane >> 3) & 1, lhi = lane >> 4;
    int q0 = qt * 128;
    const float scl = 0.0625f;         // 1/sqrt(256)

    // Stage Q [32 d][128 q] bf16 (direct cvt copy)
    #pragma unroll
    for (int r = 0; r < 4; r++) {
        int idx = tid + r * 256;
        int row = idx >> 5, c4 = (idx & 31) << 2;
        float4 v = *(const float4*)(Qg + (size_t)row * SSZ + q0 + c4);
        *(uint2*)(sm.raw + row * 272 + c4 * 2) =
            make_uint2(packbf(v.x, v.y), packbf(v.z, v.w));
    }

    float m0r = -1e30f, m1r = -1e30f, l0 = 0.f, l1 = 0.f;
    float oacc[4][4];
    #pragma unroll
    for (int j = 0; j < 4; j++)
        #pragma unroll
        for (int c = 0; c < 4; c++) oacc[j][c] = 0.f;

    for (int kt = 0; kt < 8; kt++) {
        int k0c = kt * 128;
        __syncthreads();
        // Stage K, V tiles [32 d][128 kpos]
        #pragma unroll
        for (int r = 0; r < 4; r++) {
            int idx = tid + r * 256;
            int row = idx >> 5, c4 = (idx & 31) << 2;
            float4 kv = *(const float4*)(Kg + (size_t)row * SSZ + k0c + c4);
            float4 vv = *(const float4*)(Vg + (size_t)row * SSZ + k0c + c4);
            *(uint2*)(sm.raw + ATT_TILE + row * 272 + c4 * 2) =
                make_uint2(packbf(kv.x, kv.y), packbf(kv.z, kv.w));
            *(uint2*)(sm.raw + 2 * ATT_TILE + row * 272 + c4 * 2) =
                make_uint2(packbf(vv.x, vv.y), packbf(vv.z, vv.w));
        }
        __syncthreads();

        // S = Q^T K : m=16 q rows/warp, n=128 kpos, k=d(32)
        float sacc[16][4];
        #pragma unroll
        for (int nj = 0; nj < 16; nj++)
            #pragma unroll
            for (int c = 0; c < 4; c++) sacc[nj][c] = 0.f;
        #pragma unroll
        for (int kk = 0; kk < 2; kk++) {
            uint32_t qf[4];
            {
                int row = kk * 16 + l7 + lhi * 8;       // d index
                int col = wid * 16 + lb * 8;            // q index
                ldmx4t(qf, sQ + row * 272 + col * 2);
            }
            int krow = kk * 16 + l7 + lb * 8;
            #pragma unroll
            for (int njp = 0; njp < 8; njp++) {
                uint32_t kf[4];
                int col = njp * 16 + lhi * 8;
                ldmx4t(kf, sK + krow * 272 + col * 2);
                mma_bf16(sacc[njp * 2],     qf, &kf[0]);
                mma_bf16(sacc[njp * 2 + 1], qf, &kf[2]);
            }
        }

        // Online softmax (warp-local)
        float mx0 = -1e30f, mx1 = -1e30f;
        #pragma unroll
        for (int nj = 0; nj < 16; nj++) {
            mx0 = fmaxf(mx0, fmaxf(sacc[nj][0], sacc[nj][1]));
            mx1 = fmaxf(mx1, fmaxf(sacc[nj][2], sacc[nj][3]));
        }
        mx0 *= scl; mx1 *= scl;
        #pragma unroll
        for (int o = 1; o < 4; o <<= 1) {
            mx0 = fmaxf(mx0, __shfl_xor_sync(0xffffffffu, mx0, o));
            mx1 = fmaxf(mx1, __shfl_xor_sync(0xffffffffu, mx1, o));
        }
        float mn0 = fmaxf(m0r, mx0), mn1 = fmaxf(m1r, mx1);
        float al0 = __expf(m0r - mn0), al1 = __expf(m1r - mn1);
        float s0 = 0.f, s1 = 0.f;
        #pragma unroll
        for (int nj = 0; nj < 16; nj++) {
            float p0f = __expf(sacc[nj][0] * scl - mn0);
            float p1f = __expf(sacc[nj][1] * scl - mn0);
            float p2f = __expf(sacc[nj][2] * scl - mn1);
            float p3f = __expf(sacc[nj][3] * scl - mn1);
            s0 += p0f + p1f; s1 += p2f + p3f;
            sacc[nj][0] = p0f; sacc[nj][1] = p1f;
            sacc[nj][2] = p2f; sacc[nj][3] = p3f;
        }
        #pragma unroll
        for (int o = 1; o < 4; o <<= 1) {
            s0 += __shfl_xor_sync(0xffffffffu, s0, o);
            s1 += __shfl_xor_sync(0xffffffffu, s1, o);
        }
        l0 = l0 * al0 + s0; l1 = l1 * al1 + s1;
        m0r = mn0; m1r = mn1;
        #pragma unroll
        for (int nj = 0; nj < 4; nj++) {
            oacc[nj][0] *= al0; oacc[nj][1] *= al0;
            oacc[nj][2] *= al1; oacc[nj][3] *= al1;
        }

        // O += P V^T : m=16 q, n=32 d, k=128 kpos. P from registers.
        #pragma unroll
        for (int kk = 0; kk < 8; kk++) {
            uint32_t af[4];
            af[0] = packbf(sacc[2 * kk][0],     sacc[2 * kk][1]);
            af[1] = packbf(sacc[2 * kk][2],     sacc[2 * kk][3]);
            af[2] = packbf(sacc[2 * kk + 1][0], sacc[2 * kk + 1][1]);
            af[3] = packbf(sacc[2 * kk + 1][2], sacc[2 * kk + 1][3]);
            int col = kk * 16 + lb * 8;                 // kpos
            int rbase = l7 + lhi * 8;                   // d
            uint32_t vf0[4], vf1[4];
            ldmx4(vf0, sV + rbase * 272 + col * 2);
            ldmx4(vf1, sV + (rbase + 16) * 272 + col * 2);
            mma_bf16(oacc[0], af, &vf0[0]);
            mma_bf16(oacc[1], af, &vf0[2]);
            mma_bf16(oacc[2], af, &vf1[0]);
            mma_bf16(oacc[3], af, &vf1[2]);
        }
    }

    // Normalize + transpose to [d][q] (SMEM reuse), coalesced store.
    float il0 = 1.f / l0, il1 = 1.f / l1;
    int r0g = wid * 16 + lq;
    __syncthreads();
    #pragma unroll
    for (int nj = 0; nj < 4; nj++) {
        int d0 = nj * 8 + (lr << 1);
        sm.Ot[d0 * 132 + r0g]           = oacc[nj][0] * il0;
        sm.Ot[(d0 + 1) * 132 + r0g]     = oacc[nj][1] * il0;
        sm.Ot[d0 * 132 + r0g + 8]       = oacc[nj][2] * il1;
        sm.Ot[(d0 + 1) * 132 + r0g + 8] = oacc[nj][3] * il1;
    }
    __syncthreads();
    #pragma unroll
    for (int r = 0; r < 4; r++) {
        int idx = tid + r * 256;
        int row = idx >> 5, c4 = (idx & 31) << 2;
        *(float4*)(outb + ((size_t)b * CC + h * 32 + row) * SSZ + q0 + c4) =
            *(float4*)&sm.Ot[row * 132 + c4];
    }
}

// ---------------------------------------------------------------------------
extern "C" void kernel_launch(void* const* d_in, const int* in_sizes, int n_in,
                              void* d_out, int out_size) {
    const float* xA    = (const float*)d_in[0];
    const float* xB    = (const float*)d_in[1];
    const float* gA    = (const float*)d_in[2];
    const float* bA    = (const float*)d_in[3];
    const float* gB    = (const float*)d_in[4];
    const float* bB    = (const float*)d_in[5];
    const float* WqkvA = (const float*)d_in[6];
    const float* WqkvB = (const float*)d_in[7];
    const float* WoutA = (const float*)d_in[8];
    const float* boutA = (const float*)d_in[9];
    const float* WoutB = (const float*)d_in[10];
    const float* boutB = (const float*)d_in[11];
    float* out = (float*)d_out;

    void *pn, *pq, *pa;
    cudaGetSymbolAddress(&pn, g_norm);
    cudaGetSymbolAddress(&pq, g_qkv);
    cudaGetSymbolAddress(&pa, g_attn);
    float* normA = (float*)pn;
    float* normB = normA + (size_t)BSZ * CC * SSZ;
    float* qkvA  = (float*)pq;
    float* qkvB  = qkvA + (size_t)BSZ * 3 * CC * SSZ;
    float* attnA = (float*)pa;
    float* attnB = attnA + (size_t)BSZ * CC * SSZ;

    const long CS = (long)CC * SSZ;
    const long Q3 = (long)3 * CC * SSZ;

    groupnorm_kernel<<<BSZ * NG, 256>>>(xA, gA, bA, normA);
    groupnorm_kernel<<<BSZ * NG, 256>>>(xB, gB, bB, normB);

    dim3 gq(8, 6, BSZ);
    gemm_bf16<false><<<gq, 256>>>(WqkvA, normA, qkvA, nullptr, nullptr, CS, Q3, 0);
    gemm_bf16<false><<<gq, 256>>>(WqkvB, normB, qkvB, nullptr, nullptr, CS, Q3, 0);

    dim3 ga(8, BSZ * NHD);
    attn_bf16<<<ga, 256>>>(qkvB, qkvA, attnA);
    attn_bf16<<<ga, 256>>>(qkvA, qkvB, attnB);

    dim3 gp(8, 2, BSZ);
    gemm_bf16<true><<<gp, 256>>>(WoutA, attnA, out, boutA, normA, CS, CS, CS);
    gemm_bf16<true><<<gp, 256>>>(WoutB, attnB, out + (size_t)BSZ * CC * SSZ,
                                 boutB, normB, CS, CS, CS);
}

// round 6
// speedup vs baseline: 6.7098x; 1.3436x over previous
#include <cuda_runtime.h>
#include <cuda_bf16.h>
#include <math.h>
#include <stdint.h>

#define BSZ 16
#define CC  256
#define SSZ 1024
#define NHD 8
#define NG  16
#define CPG 16
#define EPSV 1e-5f

// Scratch (allocation-free per harness rules)
__device__ __align__(128) float         g_norm  [2 * BSZ * CC * SSZ];
__device__ __align__(128) __nv_bfloat16 g_normbf[2 * BSZ * CC * SSZ];
__device__ __align__(128) __nv_bfloat16 g_qkvbf [2 * BSZ * 3 * CC * SSZ];
__device__ __align__(128) __nv_bfloat16 g_attnbf[2 * BSZ * CC * SSZ];
__device__ __align__(128) __nv_bfloat16 g_wbf   [2 * 3 * CC * CC + 2 * CC * CC];

__device__ __forceinline__ uint32_t packbf(float lo, float hi) {
    __nv_bfloat162 h = __floats2bfloat162_rn(lo, hi);
    return *(uint32_t*)&h;
}
__device__ __forceinline__ float ex2f(float x) {
    float y;
    asm("ex2.approx.ftz.f32 %0, %1;" : "=f"(y) : "f"(x));
    return y;
}
__device__ __forceinline__ void mma_bf16(float d[4], const uint32_t a[4],
                                         const uint32_t b[2]) {
    asm volatile(
        "mma.sync.aligned.m16n8k16.row.col.f32.bf16.bf16.f32 "
        "{%0,%1,%2,%3}, {%4,%5,%6,%7}, {%8,%9}, {%0,%1,%2,%3};\n"
        : "+f"(d[0]), "+f"(d[1]), "+f"(d[2]), "+f"(d[3])
        : "r"(a[0]), "r"(a[1]), "r"(a[2]), "r"(a[3]), "r"(b[0]), "r"(b[1]));
}
__device__ __forceinline__ void ldmx4(uint32_t r[4], uint32_t addr) {
    asm volatile("ldmatrix.sync.aligned.m8n8.x4.shared.b16 {%0,%1,%2,%3}, [%4];"
                 : "=r"(r[0]), "=r"(r[1]), "=r"(r[2]), "=r"(r[3]) : "r"(addr));
}
__device__ __forceinline__ void ldmx4t(uint32_t r[4], uint32_t addr) {
    asm volatile("ldmatrix.sync.aligned.m8n8.x4.trans.shared.b16 {%0,%1,%2,%3}, [%4];"
                 : "=r"(r[0]), "=r"(r[1]), "=r"(r[2]), "=r"(r[3]) : "r"(addr));
}
__device__ __forceinline__ void cpa16(uint32_t dst, const void* src) {
    asm volatile("cp.async.cg.shared.global [%0], [%1], 16;\n"
                 :: "r"(dst), "l"(src));
}
#define CP_COMMIT() asm volatile("cp.async.commit_group;\n" ::)
#define CP_WAIT(n)  asm volatile("cp.async.wait_group %0;\n" :: "n"(n))

// ---------------------------------------------------------------------------
// fp32 -> bf16 bulk convert (weights, once per launch)
// ---------------------------------------------------------------------------
__global__ void cvt_kernel(const float* __restrict__ s,
                           __nv_bfloat16* __restrict__ d, int n4) {
    int i = blockIdx.x * blockDim.x + threadIdx.x;
    if (i < n4) {
        float4 v = ((const float4*)s)[i];
        *(uint2*)(d + (size_t)i * 4) =
            make_uint2(packbf(v.x, v.y), packbf(v.z, v.w));
    }
}

// ---------------------------------------------------------------------------
// GroupNorm: writes fp32 (residual) + bf16 (GEMM operand)
// ---------------------------------------------------------------------------
__global__ void groupnorm_kernel(const float* __restrict__ x,
                                 const float* __restrict__ gamma,
                                 const float* __restrict__ beta,
                                 float* __restrict__ out,
                                 __nv_bfloat16* __restrict__ outb) {
    int bg = blockIdx.x;
    int b = bg / NG, g = bg % NG;
    const int n = CPG * SSZ;
    size_t off = (size_t)(b * CC + g * CPG) * SSZ;
    const float* xp = x + off;
    int tid = threadIdx.x;

    const float4* x4 = (const float4*)xp;
    float s = 0.f, s2 = 0.f;
    #pragma unroll 4
    for (int i = tid; i < n / 4; i += 256) {
        float4 v = x4[i];
        s  += v.x + v.y + v.z + v.w;
        s2 += v.x * v.x + v.y * v.y + v.z * v.z + v.w * v.w;
    }
    __shared__ float rs[256], rs2[256];
    rs[tid] = s; rs2[tid] = s2;
    __syncthreads();
    for (int o = 128; o > 0; o >>= 1) {
        if (tid < o) { rs[tid] += rs[tid + o]; rs2[tid] += rs2[tid + o]; }
        __syncthreads();
    }
    float mu = rs[0] / (float)n;
    float var = rs2[0] / (float)n - mu * mu;
    float rstd = rsqrtf(var + EPSV);

    float4* o4 = (float4*)(out + off);
    __nv_bfloat16* ob = outb + off;
    for (int i = tid; i < n / 4; i += 256) {
        int c = g * CPG + (i >> 8);
        float sc = gamma[c] * rstd;
        float sh = beta[c] - mu * sc;
        float4 v = x4[i];
        float4 r;
        r.x = v.x * sc + sh; r.y = v.y * sc + sh;
        r.z = v.z * sc + sh; r.w = v.w * sc + sh;
        o4[i] = r;
        *(uint2*)(ob + (size_t)i * 4) =
            make_uint2(packbf(r.x, r.y), packbf(r.z, r.w));
    }
}

// ---------------------------------------------------------------------------
// bf16 GEMM, cp.async 3-stage. C = A[Mx256] * B[256x1024].
// As: [m=128][k=32] row 80B; Bs: [k=32][n=128] row 272B. Output bf16 or fp32.
// ---------------------------------------------------------------------------
#define GA_BYTES (128 * 80)
#define GB_BYTES (32 * 272)
#define GBUF (GA_BYTES + GB_BYTES)
#define GEMM_SMEM (3 * GBUF)

__device__ __forceinline__ void gemm_stage(uint32_t sbuf,
                                           const __nv_bfloat16* A,
                                           const __nv_bfloat16* Bp,
                                           int m0, int n0, int k0, int tid) {
    #pragma unroll
    for (int r = 0; r < 2; r++) {
        int idx = tid + r * 256;
        int row = idx >> 2, ch = idx & 3;            // 128 rows x 4 chunks
        cpa16(sbuf + row * 80 + ch * 16,
              A + (size_t)(m0 + row) * 256 + k0 + ch * 8);
    }
    #pragma unroll
    for (int r = 0; r < 2; r++) {
        int idx = tid + r * 256;
        int krow = idx >> 4, ch = idx & 15;          // 32 rows x 16 chunks
        cpa16(sbuf + GA_BYTES + krow * 272 + ch * 16,
              Bp + (size_t)(k0 + krow) * 1024 + n0 + ch * 8);
    }
}

template <bool EPI>
__global__ __launch_bounds__(256, 2) void gemm_bf16(
    const __nv_bfloat16* __restrict__ A, const __nv_bfloat16* __restrict__ Bm,
    void* __restrict__ Cm, const float* __restrict__ bias,
    const float* __restrict__ res, long strideB, long strideC, long strideR) {
    const int N = 1024;
    int bz = blockIdx.z;
    const __nv_bfloat16* Bp = Bm + (size_t)bz * strideB;
    const float* Rp = EPI ? (res + (size_t)bz * strideR) : nullptr;
    int m0 = blockIdx.y * 128, n0 = blockIdx.x * 128;

    extern __shared__ __align__(16) uint8_t smem[];
    uint32_t sbase = (uint32_t)__cvta_generic_to_shared(smem);

    int tid = threadIdx.x;
    int lane = tid & 31, wid = tid >> 5;
    int wy = wid >> 2, wx = wid & 3;
    int lq = lane >> 2, lr = lane & 3;
    int l7 = lane & 7, lb = (lane >> 3) & 1, lhi = lane >> 4;

    float acc[4][4][4];
    #pragma unroll
    for (int i = 0; i < 4; i++)
        #pragma unroll
        for (int j = 0; j < 4; j++)
            #pragma unroll
            for (int c = 0; c < 4; c++) acc[i][j][c] = 0.f;

    gemm_stage(sbase, A, Bp, m0, n0, 0, tid);  CP_COMMIT();
    gemm_stage(sbase + GBUF, A, Bp, m0, n0, 32, tid);  CP_COMMIT();

    #pragma unroll
    for (int it = 0; it < 8; it++) {
        if (it == 7) { CP_WAIT(0); } else { CP_WAIT(1); }
        __syncthreads();
        if (it < 6) {
            gemm_stage(sbase + ((it + 2) % 3) * GBUF, A, Bp, m0, n0,
                       (it + 2) * 32, tid);
            CP_COMMIT();
        }
        uint32_t sA = sbase + (it % 3) * GBUF;
        uint32_t sB = sA + GA_BYTES;
        #pragma unroll
        for (int kk = 0; kk < 2; kk++) {
            uint32_t af[4][4], bf[2][4];
            #pragma unroll
            for (int mi = 0; mi < 4; mi++) {
                int row = wy * 64 + mi * 16 + l7 + lb * 8;
                int col = kk * 16 + lhi * 8;
                ldmx4(af[mi], sA + row * 80 + col * 2);
            }
            #pragma unroll
            for (int njp = 0; njp < 2; njp++) {
                int row = kk * 16 + l7 + lb * 8;
                int col = wx * 32 + njp * 16 + lhi * 8;
                ldmx4t(bf[njp], sB + row * 272 + col * 2);
            }
            #pragma unroll
            for (int mi = 0; mi < 4; mi++)
                #pragma unroll
                for (int njp = 0; njp < 2; njp++) {
                    mma_bf16(acc[mi][njp * 2],     af[mi], &bf[njp][0]);
                    mma_bf16(acc[mi][njp * 2 + 1], af[mi], &bf[njp][2]);
                }
        }
    }

    if (EPI) {
        float* Cp = (float*)Cm + (size_t)bz * strideC;
        #pragma unroll
        for (int mi = 0; mi < 4; mi++) {
            #pragma unroll
            for (int nj = 0; nj < 4; nj++) {
                int m = m0 + wy * 64 + mi * 16 + lq;
                int col = n0 + wx * 32 + nj * 8 + (lr << 1);
                float b0 = bias[m], b1 = bias[m + 8];
                float2 r0 = *(const float2*)(Rp + (size_t)m * N + col);
                float2 r1 = *(const float2*)(Rp + (size_t)(m + 8) * N + col);
                float2 v0 = make_float2(acc[mi][nj][0] + b0 + r0.x,
                                        acc[mi][nj][1] + b0 + r0.y);
                float2 v1 = make_float2(acc[mi][nj][2] + b1 + r1.x,
                                        acc[mi][nj][3] + b1 + r1.y);
                *(float2*)(Cp + (size_t)m * N + col) = v0;
                *(float2*)(Cp + (size_t)(m + 8) * N + col) = v1;
            }
        }
    } else {
        __nv_bfloat16* Cp = (__nv_bfloat16*)Cm + (size_t)bz * strideC;
        #pragma unroll
        for (int mi = 0; mi < 4; mi++) {
            #pragma unroll
            for (int nj = 0; nj < 4; nj++) {
                int m = m0 + wy * 64 + mi * 16 + lq;
                int col = n0 + wx * 32 + nj * 8 + (lr << 1);
                *(uint32_t*)(Cp + (size_t)m * N + col) =
                    packbf(acc[mi][nj][0], acc[mi][nj][1]);
                *(uint32_t*)(Cp + (size_t)(m + 8) * N + col) =
                    packbf(acc[mi][nj][2], acc[mi][nj][3]);
            }
        }
    }
}

// ---------------------------------------------------------------------------
// bf16 flash attention, cp.async 3-stage K/V, fixed-max softmax.
// Tiles [d=32][x=128] bf16 row 272B. Q/K frags ldmatrix.trans, V ldmatrix.
// ---------------------------------------------------------------------------
#define ATT_T   8704                    // one 32x272B tile
#define ATT_SMEM (ATT_T + 3 * 2 * ATT_T)  // Q + 3 stages of (K,V)

__device__ __forceinline__ void attn_stage_kv(uint32_t sK,
                                              const __nv_bfloat16* Kg,
                                              const __nv_bfloat16* Vg,
                                              int k0c, int tid) {
    #pragma unroll
    for (int r = 0; r < 2; r++) {
        int idx = tid + r * 256;
        int row = idx >> 4, ch = idx & 15;           // 32 rows x 16 chunks
        cpa16(sK + row * 272 + ch * 16,
              Kg + (size_t)row * SSZ + k0c + ch * 8);
        cpa16(sK + ATT_T + row * 272 + ch * 16,
              Vg + (size_t)row * SSZ + k0c + ch * 8);
    }
}

__global__ __launch_bounds__(256, 2) void attn_bf16(
    const __nv_bfloat16* __restrict__ qkv_q,
    const __nv_bfloat16* __restrict__ qkv_kv,
    __nv_bfloat16* __restrict__ outb) {
    extern __shared__ __align__(16) uint8_t smraw[];
    uint32_t sQ = (uint32_t)__cvta_generic_to_shared(smraw);

    int qt = blockIdx.x;
    int bh = blockIdx.y;
    int b = bh >> 3, h = bh & 7;
    size_t base = (size_t)b * 3 * CC * SSZ + (size_t)h * 96 * SSZ;
    const __nv_bfloat16* Qg = qkv_q  + base;
    const __nv_bfloat16* Kg = qkv_kv + base + 32 * SSZ;
    const __nv_bfloat16* Vg = qkv_kv + base + 64 * SSZ;

    int tid = threadIdx.x;
    int lane = tid & 31, wid = tid >> 5;
    int lq = lane >> 2, lr = lane & 3;
    int l7 = lane & 7, lb = (lane >> 3) & 1, lhi = lane >> 4;
    int q0 = qt * 128;
    const float c2 = 0.0625f * 1.44269504089f;   // scale * log2(e)

    // Prologue: Q + (K0,V0) as group 0; (K1,V1) as group 1
    #pragma unroll
    for (int r = 0; r < 2; r++) {
        int idx = tid + r * 256;
        int row = idx >> 4, ch = idx & 15;
        cpa16(sQ + row * 272 + ch * 16, Qg + (size_t)row * SSZ + q0 + ch * 8);
    }
    attn_stage_kv(sQ + ATT_T, Kg, Vg, 0, tid);
    CP_COMMIT();
    attn_stage_kv(sQ + ATT_T + 2 * ATT_T, Kg, Vg, 128, tid);
    CP_COMMIT();

    float l0 = 0.f, l1 = 0.f;
    float oacc[4][4];
    #pragma unroll
    for (int j = 0; j < 4; j++)
        #pragma unroll
        for (int c = 0; c < 4; c++) oacc[j][c] = 0.f;

    for (int kt = 0; kt < 8; kt++) {
        if (kt == 7) { CP_WAIT(0); } else { CP_WAIT(1); }
        __syncthreads();
        if (kt < 6) {
            attn_stage_kv(sQ + ATT_T + ((kt + 2) % 3) * 2 * ATT_T,
                          Kg, Vg, (kt + 2) * 128, tid);
            CP_COMMIT();
        }
        uint32_t sK = sQ + ATT_T + (kt % 3) * 2 * ATT_T;
        uint32_t sV = sK + ATT_T;

        // S = Q^T K
        float sacc[16][4];
        #pragma unroll
        for (int nj = 0; nj < 16; nj++)
            #pragma unroll
            for (int c = 0; c < 4; c++) sacc[nj][c] = 0.f;
        #pragma unroll
        for (int kk = 0; kk < 2; kk++) {
            uint32_t qf[4];
            {
                int row = kk * 16 + l7 + lhi * 8;        // d
                int col = wid * 16 + lb * 8;             // q
                ldmx4t(qf, sQ + row * 272 + col * 2);
            }
            int krow = kk * 16 + l7 + lb * 8;
            #pragma unroll
            for (int njp = 0; njp < 8; njp++) {
                uint32_t kf[4];
                int col = njp * 16 + lhi * 8;
                ldmx4t(kf, sK + krow * 272 + col * 2);
                mma_bf16(sacc[njp * 2],     qf, &kf[0]);
                mma_bf16(sacc[njp * 2 + 1], qf, &kf[2]);
            }
        }

        // Fixed-max softmax: p = 2^(s*c2); thread-local l accumulation
        #pragma unroll
        for (int nj = 0; nj < 16; nj++) {
            float p0 = ex2f(sacc[nj][0] * c2);
            float p1 = ex2f(sacc[nj][1] * c2);
            float p2 = ex2f(sacc[nj][2] * c2);
            float p3 = ex2f(sacc[nj][3] * c2);
            l0 += p0 + p1; l1 += p2 + p3;
            sacc[nj][0] = p0; sacc[nj][1] = p1;
            sacc[nj][2] = p2; sacc[nj][3] = p3;
        }

        // O += P V^T (P from registers)
        #pragma unroll
        for (int kk = 0; kk < 8; kk++) {
            uint32_t af[4];
            af[0] = packbf(sacc[2 * kk][0],     sacc[2 * kk][1]);
            af[1] = packbf(sacc[2 * kk][2],     sacc[2 * kk][3]);
            af[2] = packbf(sacc[2 * kk + 1][0], sacc[2 * kk + 1][1]);
            af[3] = packbf(sacc[2 * kk + 1][2], sacc[2 * kk + 1][3]);
            int col = kk * 16 + lb * 8;                  // kpos
            int rbase = l7 + lhi * 8;                    // d
            uint32_t vf0[4], vf1[4];
            ldmx4(vf0, sV + rbase * 272 + col * 2);
            ldmx4(vf1, sV + (rbase + 16) * 272 + col * 2);
            mma_bf16(oacc[0], af, &vf0[0]);
            mma_bf16(oacc[1], af, &vf0[2]);
            mma_bf16(oacc[2], af, &vf1[0]);
            mma_bf16(oacc[3], af, &vf1[2]);
        }
    }

    // Reduce l across the 4 lanes sharing each q row
    l0 += __shfl_xor_sync(0xffffffffu, l0, 1);
    l0 += __shfl_xor_sync(0xffffffffu, l0, 2);
    l1 += __shfl_xor_sync(0xffffffffu, l1, 1);
    l1 += __shfl_xor_sync(0xffffffffu, l1, 2);
    float il0 = 1.f / l0, il1 = 1.f / l1;

    // Transpose to [d][q] bf16 in SMEM, then coalesced bf16 store
    __nv_bfloat16* O16 = (__nv_bfloat16*)smraw;   // [32][136]
    int r0g = wid * 16 + lq;
    __syncthreads();
    #pragma unroll
    for (int nj = 0; nj < 4; nj++) {
        int d0 = nj * 8 + (lr << 1);
        O16[d0 * 136 + r0g]           = __float2bfloat16(oacc[nj][0] * il0);
        O16[(d0 + 1) * 136 + r0g]     = __float2bfloat16(oacc[nj][1] * il0);
        O16[d0 * 136 + r0g + 8]       = __float2bfloat16(oacc[nj][2] * il1);
        O16[(d0 + 1) * 136 + r0g + 8] = __float2bfloat16(oacc[nj][3] * il1);
    }
    __syncthreads();
    #pragma unroll
    for (int r = 0; r < 2; r++) {
        int idx = tid + r * 256;
        int row = idx >> 4, ch = idx & 15;       // 32 rows x 16 chunks of 8 bf16
        *(uint4*)(outb + ((size_t)b * CC + h * 32 + row) * SSZ + q0 + ch * 8) =
            *(uint4*)&O16[row * 136 + ch * 8];
    }
}

// ---------------------------------------------------------------------------
extern "C" void kernel_launch(void* const* d_in, const int* in_sizes, int n_in,
                              void* d_out, int out_size) {
    const float* xA    = (const float*)d_in[0];
    const float* xB    = (const float*)d_in[1];
    const float* gA    = (const float*)d_in[2];
    const float* bA    = (const float*)d_in[3];
    const float* gB    = (const float*)d_in[4];
    const float* bB    = (const float*)d_in[5];
    const float* WqkvA = (const float*)d_in[6];
    const float* WqkvB = (const float*)d_in[7];
    const float* WoutA = (const float*)d_in[8];
    const float* boutA = (const float*)d_in[9];
    const float* WoutB = (const float*)d_in[10];
    const float* boutB = (const float*)d_in[11];
    float* out = (float*)d_out;

    void *pn, *pnb, *pq, *pa, *pw;
    cudaGetSymbolAddress(&pn,  g_norm);
    cudaGetSymbolAddress(&pnb, g_normbf);
    cudaGetSymbolAddress(&pq,  g_qkvbf);
    cudaGetSymbolAddress(&pa,  g_attnbf);
    cudaGetSymbolAddress(&pw,  g_wbf);
    float* normA = (float*)pn;
    float* normB = normA + (size_t)BSZ * CC * SSZ;
    __nv_bfloat16* normbfA = (__nv_bfloat16*)pnb;
    __nv_bfloat16* normbfB = normbfA + (size_t)BSZ * CC * SSZ;
    __nv_bfloat16* qkvA = (__nv_bfloat16*)pq;
    __nv_bfloat16* qkvB = qkvA + (size_t)BSZ * 3 * CC * SSZ;
    __nv_bfloat16* attnA = (__nv_bfloat16*)pa;
    __nv_bfloat16* attnB = attnA + (size_t)BSZ * CC * SSZ;
    __nv_bfloat16* wqA = (__nv_bfloat16*)pw;            // 768*256
    __nv_bfloat16* wqB = wqA + 3 * CC * CC;
    __nv_bfloat16* woA = wqB + 3 * CC * CC;             // 256*256
    __nv_bfloat16* woB = woA + CC * CC;

    const long CS = (long)CC * SSZ;
    const long Q3 = (long)3 * CC * SSZ;

    cudaFuncSetAttribute(gemm_bf16<false>,
                         cudaFuncAttributeMaxDynamicSharedMemorySize, GEMM_SMEM);
    cudaFuncSetAttribute(gemm_bf16<true>,
                         cudaFuncAttributeMaxDynamicSharedMemorySize, GEMM_SMEM);
    cudaFuncSetAttribute(attn_bf16,
                         cudaFuncAttributeMaxDynamicSharedMemorySize, ATT_SMEM);

    // 0) Weight conversion (once per graph replay; cheap)
    cvt_kernel<<<192, 256>>>(WqkvA, wqA, 3 * CC * CC / 4);
    cvt_kernel<<<192, 256>>>(WqkvB, wqB, 3 * CC * CC / 4);
    cvt_kernel<<<64, 256>>>(WoutA, woA, CC * CC / 4);
    cvt_kernel<<<64, 256>>>(WoutB, woB, CC * CC / 4);

    // 1) GroupNorm (fp32 + bf16)
    groupnorm_kernel<<<BSZ * NG, 256>>>(xA, gA, bA, normA, normbfA);
    groupnorm_kernel<<<BSZ * NG, 256>>>(xB, gB, bB, normB, normbfB);

    // 2) QKV projections -> bf16
    dim3 gq(8, 6, BSZ);
    gemm_bf16<false><<<gq, 256, GEMM_SMEM>>>(wqA, normbfA, qkvA,
                                             nullptr, nullptr, CS, Q3, 0);
    gemm_bf16<false><<<gq, 256, GEMM_SMEM>>>(wqB, normbfB, qkvB,
                                             nullptr, nullptr, CS, Q3, 0);

    // 3) Cross attention -> bf16
    dim3 ga(8, BSZ * NHD);
    attn_bf16<<<ga, 256, ATT_SMEM>>>(qkvB, qkvA, attnA);
    attn_bf16<<<ga, 256, ATT_SMEM>>>(qkvA, qkvB, attnB);

    // 4) Output projection + bias + residual(norm) -> fp32
    dim3 gp(8, 2, BSZ);
    gemm_bf16<true><<<gp, 256, GEMM_SMEM>>>(woA, attnA, out,
                                            boutA, normA, CS, CS, CS);
    gemm_bf16<true><<<gp, 256, GEMM_SMEM>>>(woB, attnB,
                                            out + (size_t)BSZ * CC * SSZ,
                                            boutB, normB, CS, CS, CS);
}

// round 7
// speedup vs baseline: 7.5628x; 1.1271x over previous
#include <cuda_runtime.h>
#include <cuda_bf16.h>
#include <math.h>
#include <stdint.h>

#define BSZ 16
#define CC  256
#define SSZ 1024
#define NHD 8
#define NG  16
#define CPG 16
#define EPSV 1e-5f

// scale(1/sqrt(256)) * log2(e), folded into Q at qkv-GEMM epilogue
#define QSC 0.09016844005556021f

__device__ __align__(128) float         g_norm  [2 * BSZ * CC * SSZ];
__device__ __align__(128) __nv_bfloat16 g_normbf[2 * BSZ * CC * SSZ];
__device__ __align__(128) __nv_bfloat16 g_qkvbf [2 * BSZ * 3 * CC * SSZ];
__device__ __align__(128) __nv_bfloat16 g_attnbf[2 * BSZ * CC * SSZ];
__device__ __align__(128) __nv_bfloat16 g_wbf   [2 * 3 * CC * CC + 2 * CC * CC];

__device__ __forceinline__ uint32_t packbf(float lo, float hi) {
    __nv_bfloat162 h = __floats2bfloat162_rn(lo, hi);
    return *(uint32_t*)&h;
}
__device__ __forceinline__ float ex2f(float x) {
    float y;
    asm("ex2.approx.ftz.f32 %0, %1;" : "=f"(y) : "f"(x));
    return y;
}
__device__ __forceinline__ void mma_bf16(float d[4], const uint32_t a[4],
                                         const uint32_t b[2]) {
    asm volatile(
        "mma.sync.aligned.m16n8k16.row.col.f32.bf16.bf16.f32 "
        "{%0,%1,%2,%3}, {%4,%5,%6,%7}, {%8,%9}, {%0,%1,%2,%3};\n"
        : "+f"(d[0]), "+f"(d[1]), "+f"(d[2]), "+f"(d[3])
        : "r"(a[0]), "r"(a[1]), "r"(a[2]), "r"(a[3]), "r"(b[0]), "r"(b[1]));
}
__device__ __forceinline__ void ldmx4(uint32_t r[4], uint32_t addr) {
    asm volatile("ldmatrix.sync.aligned.m8n8.x4.shared.b16 {%0,%1,%2,%3}, [%4];"
                 : "=r"(r[0]), "=r"(r[1]), "=r"(r[2]), "=r"(r[3]) : "r"(addr));
}
__device__ __forceinline__ void ldmx4t(uint32_t r[4], uint32_t addr) {
    asm volatile("ldmatrix.sync.aligned.m8n8.x4.trans.shared.b16 {%0,%1,%2,%3}, [%4];"
                 : "=r"(r[0]), "=r"(r[1]), "=r"(r[2]), "=r"(r[3]) : "r"(addr));
}
__device__ __forceinline__ void cpa16(uint32_t dst, const void* src) {
    asm volatile("cp.async.cg.shared.global [%0], [%1], 16;\n"
                 :: "r"(dst), "l"(src));
}
#define CP_COMMIT() asm volatile("cp.async.commit_group;\n" ::)
#define CP_WAIT(n)  asm volatile("cp.async.wait_group %0;\n" :: "n"(n))

// ---------------------------------------------------------------------------
// All four weight conversions in ONE launch
// ---------------------------------------------------------------------------
__global__ void cvt_all(const float* __restrict__ wqkvA,
                        const float* __restrict__ wqkvB,
                        const float* __restrict__ woutA,
                        const float* __restrict__ woutB,
                        __nv_bfloat16* __restrict__ dq,   // 2 * 3C*C
                        __nv_bfloat16* __restrict__ do_) { // 2 * C*C
    int i = blockIdx.x * blockDim.x + threadIdx.x;   // 131072 float4 items
    const int QW = 3 * CC * CC / 4;                  // 49152
    const int OW = CC * CC / 4;                      // 16384
    const float* s; __nv_bfloat16* d; int off;
    if (i < QW)               { s = wqkvA; d = dq;               off = i; }
    else if (i < 2 * QW)      { s = wqkvB; d = dq + 4 * QW;      off = i - QW; }
    else if (i < 2 * QW + OW) { s = woutA; d = do_;              off = i - 2 * QW; }
    else                      { s = woutB; d = do_ + 4 * OW;     off = i - 2 * QW - OW; }
    float4 v = ((const float4*)s)[off];
    *(uint2*)(d + (size_t)off * 4) = make_uint2(packbf(v.x, v.y), packbf(v.z, v.w));
}

// ---------------------------------------------------------------------------
// GroupNorm, both branches in one launch, x cached in registers (1 read)
// ---------------------------------------------------------------------------
__global__ void groupnorm_kernel(const float* __restrict__ x0,
                                 const float* __restrict__ x1,
                                 const float* __restrict__ gm0,
                                 const float* __restrict__ gm1,
                                 const float* __restrict__ bt0,
                                 const float* __restrict__ bt1,
                                 float* __restrict__ out,
                                 __nv_bfloat16* __restrict__ outb) {
    int br = blockIdx.y;
    const float* x     = br ? x1 : x0;
    const float* gamma = br ? gm1 : gm0;
    const float* beta  = br ? bt1 : bt0;
    size_t broff = (size_t)br * BSZ * CC * SSZ;

    int bg = blockIdx.x;
    int b = bg / NG, g = bg % NG;
    const int n = CPG * SSZ;                       // 16384
    size_t off = broff + (size_t)(b * CC + g * CPG) * SSZ;
    int tid = threadIdx.x;

    const float4* x4 = (const float4*)(x + (size_t)(b * CC + g * CPG) * SSZ);
    float4 xv[16];
    float s = 0.f, s2 = 0.f;
    #pragma unroll
    for (int r = 0; r < 16; r++) {
        float4 v = x4[tid + r * 256];
        xv[r] = v;
        s  += v.x + v.y + v.z + v.w;
        s2 += v.x * v.x + v.y * v.y + v.z * v.z + v.w * v.w;
    }
    __shared__ float rs[256], rs2[256];
    rs[tid] = s; rs2[tid] = s2;
    __syncthreads();
    for (int o = 128; o > 0; o >>= 1) {
        if (tid < o) { rs[tid] += rs[tid + o]; rs2[tid] += rs2[tid + o]; }
        __syncthreads();
    }
    float mu = rs[0] / (float)n;
    float var = rs2[0] / (float)n - mu * mu;
    float rstd = rsqrtf(var + EPSV);

    float4* o4 = (float4*)(out + off);
    __nv_bfloat16* ob = outb + off;
    #pragma unroll
    for (int r = 0; r < 16; r++) {
        int i = tid + r * 256;
        int c = g * CPG + (i >> 8);
        float sc = gamma[c] * rstd;
        float sh = beta[c] - mu * sc;
        float4 v = xv[r];
        float4 rr;
        rr.x = v.x * sc + sh; rr.y = v.y * sc + sh;
        rr.z = v.z * sc + sh; rr.w = v.w * sc + sh;
        o4[i] = rr;
        *(uint2*)(ob + (size_t)i * 4) =
            make_uint2(packbf(rr.x, rr.y), packbf(rr.z, rr.w));
    }
}

// ---------------------------------------------------------------------------
// bf16 GEMM, cp.async 3-stage. C = A[Mx256]*B[256x1024]. z = branch*16+batch.
// EPI: +bias+residual, fp32 out. !EPI: Q rows (m%96<32) pre-scaled, bf16 out.
// ---------------------------------------------------------------------------
#define GA_BYTES (128 * 80)
#define GB_BYTES (32 * 272)
#define GBUF (GA_BYTES + GB_BYTES)
#define GEMM_SMEM (3 * GBUF)

__device__ __forceinline__ void gemm_stage(uint32_t sbuf,
                                           const __nv_bfloat16* A,
                                           const __nv_bfloat16* Bp,
                                           int m0, int n0, int k0, int tid) {
    #pragma unroll
    for (int r = 0; r < 2; r++) {
        int idx = tid + r * 256;
        int row = idx >> 2, ch = idx & 3;
        cpa16(sbuf + row * 80 + ch * 16,
              A + (size_t)(m0 + row) * 256 + k0 + ch * 8);
    }
    #pragma unroll
    for (int r = 0; r < 2; r++) {
        int idx = tid + r * 256;
        int krow = idx >> 4, ch = idx & 15;
        cpa16(sbuf + GA_BYTES + krow * 272 + ch * 16,
              Bp + (size_t)(k0 + krow) * 1024 + n0 + ch * 8);
    }
}

template <bool EPI>
__global__ __launch_bounds__(256, 2) void gemm_bf16(
    const __nv_bfloat16* __restrict__ A0, const __nv_bfloat16* __restrict__ A1,
    const __nv_bfloat16* __restrict__ B0, const __nv_bfloat16* __restrict__ B1,
    void* __restrict__ C0, void* __restrict__ C1,
    const float* __restrict__ bias0, const float* __restrict__ bias1,
    const float* __restrict__ res0, const float* __restrict__ res1,
    long strideB, long strideC) {
    const int N = 1024;
    int z = blockIdx.z;
    int br = z >> 4, bz = z & 15;
    const __nv_bfloat16* A = br ? A1 : A0;
    const __nv_bfloat16* Bp = (br ? B1 : B0) + (size_t)bz * strideB;
    int m0 = blockIdx.y * 128, n0 = blockIdx.x * 128;

    extern __shared__ __align__(16) uint8_t smem[];
    uint32_t sbase = (uint32_t)__cvta_generic_to_shared(smem);

    int tid = threadIdx.x;
    int lane = tid & 31, wid = tid >> 5;
    int wy = wid >> 2, wx = wid & 3;
    int lq = lane >> 2, lr = lane & 3;
    int l7 = lane & 7, lb = (lane >> 3) & 1, lhi = lane >> 4;

    float acc[4][4][4];
    #pragma unroll
    for (int i = 0; i < 4; i++)
        #pragma unroll
        for (int j = 0; j < 4; j++)
            #pragma unroll
            for (int c = 0; c < 4; c++) acc[i][j][c] = 0.f;

    gemm_stage(sbase, A, Bp, m0, n0, 0, tid);  CP_COMMIT();
    gemm_stage(sbase + GBUF, A, Bp, m0, n0, 32, tid);  CP_COMMIT();

    #pragma unroll
    for (int it = 0; it < 8; it++) {
        if (it == 7) { CP_WAIT(0); } else { CP_WAIT(1); }
        __syncthreads();
        if (it < 6) {
            gemm_stage(sbase + ((it + 2) % 3) * GBUF, A, Bp, m0, n0,
                       (it + 2) * 32, tid);
            CP_COMMIT();
        }
        uint32_t sA = sbase + (it % 3) * GBUF;
        uint32_t sB = sA + GA_BYTES;
        #pragma unroll
        for (int kk = 0; kk < 2; kk++) {
            uint32_t af[4][4], bf[2][4];
            #pragma unroll
            for (int mi = 0; mi < 4; mi++) {
                int row = wy * 64 + mi * 16 + l7 + lb * 8;
                int col = kk * 16 + lhi * 8;
                ldmx4(af[mi], sA + row * 80 + col * 2);
            }
            #pragma unroll
            for (int njp = 0; njp < 2; njp++) {
                int row = kk * 16 + l7 + lb * 8;
                int col = wx * 32 + njp * 16 + lhi * 8;
                ldmx4t(bf[njp], sB + row * 272 + col * 2);
            }
            #pragma unroll
            for (int mi = 0; mi < 4; mi++)
                #pragma unroll
                for (int njp = 0; njp < 2; njp++) {
                    mma_bf16(acc[mi][njp * 2],     af[mi], &bf[njp][0]);
                    mma_bf16(acc[mi][njp * 2 + 1], af[mi], &bf[njp][2]);
                }
        }
    }

    if (EPI) {
        float* Cp = (float*)(br ? C1 : C0) + (size_t)bz * strideC;
        const float* bias = br ? bias1 : bias0;
        const float* Rp = (br ? res1 : res0) + (size_t)bz * strideB;
        #pragma unroll
        for (int mi = 0; mi < 4; mi++) {
            #pragma unroll
            for (int nj = 0; nj < 4; nj++) {
                int m = m0 + wy * 64 + mi * 16 + lq;
                int col = n0 + wx * 32 + nj * 8 + (lr << 1);
                float b0 = bias[m], b1 = bias[m + 8];
                float2 r0 = *(const float2*)(Rp + (size_t)m * N + col);
                float2 r1 = *(const float2*)(Rp + (size_t)(m + 8) * N + col);
                *(float2*)(Cp + (size_t)m * N + col) =
                    make_float2(acc[mi][nj][0] + b0 + r0.x,
                                acc[mi][nj][1] + b0 + r0.y);
                *(float2*)(Cp + (size_t)(m + 8) * N + col) =
                    make_float2(acc[mi][nj][2] + b1 + r1.x,
                                acc[mi][nj][3] + b1 + r1.y);
            }
        }
    } else {
        __nv_bfloat16* Cp = (__nv_bfloat16*)(br ? C1 : C0) + (size_t)bz * strideC;
        #pragma unroll
        for (int mi = 0; mi < 4; mi++) {
            #pragma unroll
            for (int nj = 0; nj < 4; nj++) {
                int m = m0 + wy * 64 + mi * 16 + lq;
                int col = n0 + wx * 32 + nj * 8 + (lr << 1);
                float q0 = ((m % 96) < 32) ? QSC : 1.f;
                float q1 = (((m + 8) % 96) < 32) ? QSC : 1.f;
                *(uint32_t*)(Cp + (size_t)m * N + col) =
                    packbf(acc[mi][nj][0] * q0, acc[mi][nj][1] * q0);
                *(uint32_t*)(Cp + (size_t)(m + 8) * N + col) =
                    packbf(acc[mi][nj][2] * q1, acc[mi][nj][3] * q1);
            }
        }
    }
}

// ---------------------------------------------------------------------------
// bf16 flash attention, cp.async 3-stage K/V, fixed-max softmax (Q pre-scaled).
// z = branch: 0 -> (qB, kvA) -> attnA ; 1 -> (qA, kvB) -> attnB.
// ---------------------------------------------------------------------------
#define ATT_T   8704
#define ATT_SMEM (ATT_T + 3 * 2 * ATT_T)

__device__ __forceinline__ void attn_stage_kv(uint32_t sK,
                                              const __nv_bfloat16* Kg,
                                              const __nv_bfloat16* Vg,
                                              int k0c, int tid) {
    #pragma unroll
    for (int r = 0; r < 2; r++) {
        int idx = tid + r * 256;
        int row = idx >> 4, ch = idx & 15;
        cpa16(sK + row * 272 + ch * 16,
              Kg + (size_t)row * SSZ + k0c + ch * 8);
        cpa16(sK + ATT_T + row * 272 + ch * 16,
              Vg + (size_t)row * SSZ + k0c + ch * 8);
    }
}

__global__ __launch_bounds__(256, 2) void attn_bf16(
    const __nv_bfloat16* __restrict__ qkvA,
    const __nv_bfloat16* __restrict__ qkvB,
    __nv_bfloat16* __restrict__ attnA,
    __nv_bfloat16* __restrict__ attnB) {
    extern __shared__ __align__(16) uint8_t smraw[];
    uint32_t sQ = (uint32_t)__cvta_generic_to_shared(smraw);

    int brz = blockIdx.z;
    const __nv_bfloat16* qsrc = brz ? qkvA : qkvB;
    const __nv_bfloat16* kvsrc = brz ? qkvB : qkvA;
    __nv_bfloat16* outb = brz ? attnB : attnA;

    int qt = blockIdx.x;
    int bh = blockIdx.y;
    int b = bh >> 3, h = bh & 7;
    size_t base = (size_t)b * 3 * CC * SSZ + (size_t)h * 96 * SSZ;
    const __nv_bfloat16* Qg = qsrc  + base;
    const __nv_bfloat16* Kg = kvsrc + base + 32 * SSZ;
    const __nv_bfloat16* Vg = kvsrc + base + 64 * SSZ;

    int tid = threadIdx.x;
    int lane = tid & 31, wid = tid >> 5;
    int lq = lane >> 2, lr = lane & 3;
    int l7 = lane & 7, lb = (lane >> 3) & 1, lhi = lane >> 4;
    int q0 = qt * 128;

    #pragma unroll
    for (int r = 0; r < 2; r++) {
        int idx = tid + r * 256;
        int row = idx >> 4, ch = idx & 15;
        cpa16(sQ + row * 272 + ch * 16, Qg + (size_t)row * SSZ + q0 + ch * 8);
    }
    attn_stage_kv(sQ + ATT_T, Kg, Vg, 0, tid);
    CP_COMMIT();
    attn_stage_kv(sQ + ATT_T + 2 * ATT_T, Kg, Vg, 128, tid);
    CP_COMMIT();

    float l0 = 0.f, l1 = 0.f;
    float oacc[4][4];
    #pragma unroll
    for (int j = 0; j < 4; j++)
        #pragma unroll
        for (int c = 0; c < 4; c++) oacc[j][c] = 0.f;

    for (int kt = 0; kt < 8; kt++) {
        if (kt == 7) { CP_WAIT(0); } else { CP_WAIT(1); }
        __syncthreads();
        if (kt < 6) {
            attn_stage_kv(sQ + ATT_T + ((kt + 2) % 3) * 2 * ATT_T,
                          Kg, Vg, (kt + 2) * 128, tid);
            CP_COMMIT();
        }
        uint32_t sK = sQ + ATT_T + (kt % 3) * 2 * ATT_T;
        uint32_t sV = sK + ATT_T;

        float sacc[16][4];
        #pragma unroll
        for (int nj = 0; nj < 16; nj++)
            #pragma unroll
            for (int c = 0; c < 4; c++) sacc[nj][c] = 0.f;
        #pragma unroll
        for (int kk = 0; kk < 2; kk++) {
            uint32_t qf[4];
            {
                int row = kk * 16 + l7 + lhi * 8;
                int col = wid * 16 + lb * 8;
                ldmx4t(qf, sQ + row * 272 + col * 2);
            }
            int krow = kk * 16 + l7 + lb * 8;
            #pragma unroll
            for (int njp = 0; njp < 8; njp++) {
                uint32_t kf[4];
                int col = njp * 16 + lhi * 8;
                ldmx4t(kf, sK + krow * 272 + col * 2);
                mma_bf16(sacc[njp * 2],     qf, &kf[0]);
                mma_bf16(sacc[njp * 2 + 1], qf, &kf[2]);
            }
        }

        // p = 2^s (scale folded into Q)
        #pragma unroll
        for (int nj = 0; nj < 16; nj++) {
            float p0 = ex2f(sacc[nj][0]);
            float p1 = ex2f(sacc[nj][1]);
            float p2 = ex2f(sacc[nj][2]);
            float p3 = ex2f(sacc[nj][3]);
            l0 += p0 + p1; l1 += p2 + p3;
            sacc[nj][0] = p0; sacc[nj][1] = p1;
            sacc[nj][2] = p2; sacc[nj][3] = p3;
        }

        #pragma unroll
        for (int kk = 0; kk < 8; kk++) {
            uint32_t af[4];
            af[0] = packbf(sacc[2 * kk][0],     sacc[2 * kk][1]);
            af[1] = packbf(sacc[2 * kk][2],     sacc[2 * kk][3]);
            af[2] = packbf(sacc[2 * kk + 1][0], sacc[2 * kk + 1][1]);
            af[3] = packbf(sacc[2 * kk + 1][2], sacc[2 * kk + 1][3]);
            int col = kk * 16 + lb * 8;
            int rbase = l7 + lhi * 8;
            uint32_t vf0[4], vf1[4];
            ldmx4(vf0, sV + rbase * 272 + col * 2);
            ldmx4(vf1, sV + (rbase + 16) * 272 + col * 2);
            mma_bf16(oacc[0], af, &vf0[0]);
            mma_bf16(oacc[1], af, &vf0[2]);
            mma_bf16(oacc[2], af, &vf1[0]);
            mma_bf16(oacc[3], af, &vf1[2]);
        }
    }

    l0 += __shfl_xor_sync(0xffffffffu, l0, 1);
    l0 += __shfl_xor_sync(0xffffffffu, l0, 2);
    l1 += __shfl_xor_sync(0xffffffffu, l1, 1);
    l1 += __shfl_xor_sync(0xffffffffu, l1, 2);
    float il0 = 1.f / l0, il1 = 1.f / l1;

    __nv_bfloat16* O16 = (__nv_bfloat16*)smraw;   // [32][136]
    int r0g = wid * 16 + lq;
    __syncthreads();
    #pragma unroll
    for (int nj = 0; nj < 4; nj++) {
        int d0 = nj * 8 + (lr << 1);
        O16[d0 * 136 + r0g]           = __float2bfloat16(oacc[nj][0] * il0);
        O16[(d0 + 1) * 136 + r0g]     = __float2bfloat16(oacc[nj][1] * il0);
        O16[d0 * 136 + r0g + 8]       = __float2bfloat16(oacc[nj][2] * il1);
        O16[(d0 + 1) * 136 + r0g + 8] = __float2bfloat16(oacc[nj][3] * il1);
    }
    __syncthreads();
    #pragma unroll
    for (int r = 0; r < 2; r++) {
        int idx = tid + r * 256;
        int row = idx >> 4, ch = idx & 15;
        *(uint4*)(outb + ((size_t)b * CC + h * 32 + row) * SSZ + q0 + ch * 8) =
            *(uint4*)&O16[row * 136 + ch * 8];
    }
}

// ---------------------------------------------------------------------------
extern "C" void kernel_launch(void* const* d_in, const int* in_sizes, int n_in,
                              void* d_out, int out_size) {
    const float* xA    = (const float*)d_in[0];
    const float* xB    = (const float*)d_in[1];
    const float* gA    = (const float*)d_in[2];
    const float* bA    = (const float*)d_in[3];
    const float* gB    = (const float*)d_in[4];
    const float* bB    = (const float*)d_in[5];
    const float* WqkvA = (const float*)d_in[6];
    const float* WqkvB = (const float*)d_in[7];
    const float* WoutA = (const float*)d_in[8];
    const float* boutA = (const float*)d_in[9];
    const float* WoutB = (const float*)d_in[10];
    const float* boutB = (const float*)d_in[11];
    float* out = (float*)d_out;

    void *pn, *pnb, *pq, *pa, *pw;
    cudaGetSymbolAddress(&pn,  g_norm);
    cudaGetSymbolAddress(&pnb, g_normbf);
    cudaGetSymbolAddress(&pq,  g_qkvbf);
    cudaGetSymbolAddress(&pa,  g_attnbf);
    cudaGetSymbolAddress(&pw,  g_wbf);
    float* normA = (float*)pn;
    float* normB = normA + (size_t)BSZ * CC * SSZ;
    __nv_bfloat16* normbfA = (__nv_bfloat16*)pnb;
    __nv_bfloat16* normbfB = normbfA + (size_t)BSZ * CC * SSZ;
    __nv_bfloat16* qkvA = (__nv_bfloat16*)pq;
    __nv_bfloat16* qkvB = qkvA + (size_t)BSZ * 3 * CC * SSZ;
    __nv_bfloat16* attnA = (__nv_bfloat16*)pa;
    __nv_bfloat16* attnB = attnA + (size_t)BSZ * CC * SSZ;
    __nv_bfloat16* wqA = (__nv_bfloat16*)pw;
    __nv_bfloat16* wqB = wqA + 3 * CC * CC;
    __nv_bfloat16* woA = wqB + 3 * CC * CC;
    __nv_bfloat16* woB = woA + CC * CC;

    const long CS = (long)CC * SSZ;
    const long Q3 = (long)3 * CC * SSZ;

    cudaFuncSetAttribute(gemm_bf16<false>,
                         cudaFuncAttributeMaxDynamicSharedMemorySize, GEMM_SMEM);
    cudaFuncSetAttribute(gemm_bf16<true>,
                         cudaFuncAttributeMaxDynamicSharedMemorySize, GEMM_SMEM);
    cudaFuncSetAttribute(attn_bf16,
                         cudaFuncAttributeMaxDynamicSharedMemorySize, ATT_SMEM);

    // 0) All weight conversions, one launch
    cvt_all<<<512, 256>>>(WqkvA, WqkvB, WoutA, WoutB, wqA, woA);

    // 1) GroupNorm, both branches
    dim3 gn(BSZ * NG, 2);
    groupnorm_kernel<<<gn, 256>>>(xA, xB, gA, gB, bA, bB,
                                  normA, (__nv_bfloat16*)pnb);

    // 2) QKV projections, both branches (Q rows pre-scaled)
    dim3 gq(8, 6, 32);
    gemm_bf16<false><<<gq, 256, GEMM_SMEM>>>(
        wqA, wqB, normbfA, normbfB, qkvA, qkvB,
        nullptr, nullptr, nullptr, nullptr, CS, Q3);

    // 3) Cross attention, both branches
    dim3 ga(8, BSZ * NHD, 2);
    attn_bf16<<<ga, 256, ATT_SMEM>>>(qkvA, qkvB, attnA, attnB);

    // 4) Output projection + bias + residual, both branches
    dim3 gp(8, 2, 32);
    gemm_bf16<true><<<gp, 256, GEMM_SMEM>>>(
        woA, woB, attnA, attnB, out, out + (size_t)BSZ * CC * SSZ,
        boutA, boutB, normA, normB, CS, CS);
}